// round 5
// baseline (speedup 1.0000x reference)
#include <cuda_runtime.h>
#include <cstdint>

#define B_    16
#define FIN_  256
#define NTOK_ 1024
#define NH_   8
#define FH_   64
#define CIN_  258
#define CPAD_ 288
#define COUT_ 512

// ---------------------------------------------------------------------------
// Scratch (static device arrays; no allocation allowed)
// "perm" = contraction dim permuted within aligned 8-groups by
// p(k) = ((k&3)<<1)|(k>>2), so fragment pairs (t4, t4+4) sit at (2t4, 2t4+1).
__device__ float g_t[B_ * NTOK_ * CPAD_];          // [b][n][c-perm]
__device__ float g_w[3 * COUT_ * CPAD_];           // packed qkv weights [row][c-perm]
__device__ float g_wo[FIN_ * COUT_];               // packed wo [row][k-perm]
__device__ float g_q[B_ * NH_ * NTOK_ * FH_];      // [b][h][n][d-perm]
__device__ float g_k[B_ * NH_ * NTOK_ * FH_];      // [b][h][n][d-perm]
__device__ float g_v[B_ * NH_ * FH_ * NTOK_];      // [b][h][d][n-perm]
__device__ float g_o[B_ * NTOK_ * COUT_];          // [b][n][(h*64+d)-perm]

// ---------------------------------------------------------------------------
__device__ __forceinline__ int perm8(int k) { return ((k & 3) << 1) | ((k >> 2) & 1); }

__device__ __forceinline__ uint32_t smem_u32(const void* p) {
    uint32_t a;
    asm("{ .reg .u64 t; cvta.to.shared.u64 t, %1; cvt.u32.u64 %0, t; }" : "=r"(a) : "l"(p));
    return a;
}
__device__ __forceinline__ void cp16(uint32_t sdst, const void* gsrc) {
    asm volatile("cp.async.cg.shared.global [%0], [%1], 16;" :: "r"(sdst), "l"(gsrc));
}
#define CP_COMMIT() asm volatile("cp.async.commit_group;" ::: "memory")
#define CP_WAIT(n)  asm volatile("cp.async.wait_group %0;" :: "n"(n) : "memory")

// D += A*B, m16n8k8 tf32 (raw fp32 bits -> hw truncates mantissa)
__device__ __forceinline__ void mma8(float c[4], const uint32_t a[4], uint32_t b0, uint32_t b1) {
    asm volatile(
        "mma.sync.aligned.m16n8k8.row.col.f32.tf32.tf32.f32 "
        "{%0,%1,%2,%3}, {%4,%5,%6,%7}, {%8,%9}, {%0,%1,%2,%3};"
        : "+f"(c[0]), "+f"(c[1]), "+f"(c[2]), "+f"(c[3])
        : "r"(a[0]), "r"(a[1]), "r"(a[2]), "r"(a[3]), "r"(b0), "r"(b1));
}

// ---------------------------------------------------------------------------
// Kernel 0a: t_T[b][n][c-perm] = concat(x, gy, gx), zero-padded to 288.
__global__ __launch_bounds__(256) void prep_kernel(const float* __restrict__ x) {
    __shared__ float tile[32][33];
    const int nt = blockIdx.x, b = blockIdx.y;
    const int tx = threadIdx.x & 31, ty = threadIdx.x >> 5;
    const int n0 = nt * 32;
    for (int c0 = 0; c0 < CPAD_; c0 += 32) {
        for (int ci = ty; ci < 32; ci += 8) {
            const int c = c0 + ci, n = n0 + tx;
            float v = 0.f;
            if (c < FIN_)           v = x[((size_t)b * FIN_ + c) * NTOK_ + n];
            else if (c == FIN_)     v = -1.f + (2.f / 31.f) * (float)(n >> 5);
            else if (c == FIN_ + 1) v = -1.f + (2.f / 31.f) * (float)(n & 31);
            tile[ci][tx] = v;
        }
        __syncthreads();
        for (int ni = ty; ni < 32; ni += 8) {
            const int cp = c0 + (tx & ~7) + perm8(tx & 7);
            g_t[((size_t)b * NTOK_ + n0 + ni) * CPAD_ + cp] = tile[tx][ni];
        }
        __syncthreads();
    }
}

// Kernel 0b: pack q,k,v weights [1536][288], c-permuted, zero-padded.
__global__ __launch_bounds__(256) void pack_w(
    const float* __restrict__ wq, const float* __restrict__ wk, const float* __restrict__ wv)
{
    const int i = blockIdx.x * 256 + threadIdx.x;          // 1536*288
    const int r = i / CPAD_, c = i - r * CPAD_;
    const int sel = r >> 9, o = r & 511;
    const float* w = (sel == 0) ? wq : ((sel == 1) ? wk : wv);
    const int cp = (c & ~7) | perm8(c & 7);
    g_w[(size_t)r * CPAD_ + cp] = (c < CIN_) ? w[o * CIN_ + c] : 0.f;
}

// Kernel 0c: pack wo [256][512], k-permuted.
__global__ __launch_bounds__(256) void pack_wo(const float* __restrict__ wo) {
    const int i = blockIdx.x * 256 + threadIdx.x;          // 256*512
    const int r = i >> 9, c = i & 511;
    const int cp = (c & ~7) | perm8(c & 7);
    g_wo[(size_t)r * COUT_ + cp] = wo[i];
}

// ---------------------------------------------------------------------------
// GEMM: CTA 128x128, 8 warps (4m x 2n), warp 32x64, K-chunks 32, cp.async x2.
#define KP 36
__global__ __launch_bounds__(256, 2) void qkv_gemm(
    const float* __restrict__ bq, const float* __restrict__ bk, const float* __restrict__ bv)
{
    extern __shared__ uint32_t sm[];
    const int TSZ = 128 * KP;
    const uint32_t sb = smem_u32(sm);

    const int tid = threadIdx.x;
    const int warp = tid >> 5, lane = tid & 31;
    const int g = lane >> 2, t4 = lane & 3;
    const int wm = warp & 3, wn = warp >> 2;
    const int nt = blockIdx.x, mt = blockIdx.y, b = blockIdx.z;
    const int sel = mt >> 2;
    const int o0 = (mt & 3) * 128;
    const int n0 = nt * 128;
    const float* wsrc = g_w + (size_t)(sel * COUT_ + o0) * CPAD_;
    const float* bsrc = g_t + ((size_t)b * NTOK_ + n0) * CPAD_;
    const float* bias = (sel == 0) ? bq : ((sel == 1) ? bk : bv);

    auto loadAB = [&](int kc, int buf) {
        const uint32_t abase = sb + (uint32_t)(buf * 2 * TSZ) * 4;
        const uint32_t bbase = abase + (uint32_t)TSZ * 4;
        #pragma unroll
        for (int it = 0; it < 4; it++) {
            const int i = tid + it * 256;
            const int r = i >> 3, c4 = i & 7;
            cp16(abase + (uint32_t)(r * KP + c4 * 4) * 4, wsrc + (size_t)r * CPAD_ + kc * 32 + c4 * 4);
            cp16(bbase + (uint32_t)(r * KP + c4 * 4) * 4, bsrc + (size_t)r * CPAD_ + kc * 32 + c4 * 4);
        }
    };

    float c[2][8][4];
    #pragma unroll
    for (int mi = 0; mi < 2; mi++)
        #pragma unroll
        for (int nf = 0; nf < 8; nf++)
            #pragma unroll
            for (int q = 0; q < 4; q++) c[mi][nf][q] = 0.f;

    loadAB(0, 0); CP_COMMIT();

    const int NK = CPAD_ / 32;  // 9
    int buf = 0;
    for (int kc = 0; kc < NK; kc++) {
        if (kc + 1 < NK) { loadAB(kc + 1, buf ^ 1); CP_COMMIT(); CP_WAIT(1); }
        else CP_WAIT(0);
        __syncthreads();
        const uint32_t* A  = sm + buf * 2 * TSZ;
        const uint32_t* Bt = A + TSZ;
        #pragma unroll
        for (int ks = 0; ks < 4; ks++) {
            const int k0 = ks * 8 + 2 * t4;
            uint32_t a[2][4];
            #pragma unroll
            for (int mi = 0; mi < 2; mi++) {
                const int m0 = wm * 32 + mi * 16;
                const uint2 va0 = *(const uint2*)&A[(m0 + g)     * KP + k0];
                const uint2 va1 = *(const uint2*)&A[(m0 + g + 8) * KP + k0];
                a[mi][0] = va0.x; a[mi][1] = va1.x; a[mi][2] = va0.y; a[mi][3] = va1.y;
            }
            #pragma unroll
            for (int nf = 0; nf < 8; nf++) {
                const int nr = wn * 64 + nf * 8 + g;
                const uint2 vb = *(const uint2*)&Bt[nr * KP + k0];
                mma8(c[0][nf], a[0], vb.x, vb.y);
                mma8(c[1][nf], a[1], vb.x, vb.y);
            }
        }
        __syncthreads();
        buf ^= 1;
    }

    float* Cs = (float*)sm;   // 128*132*4 = 67584 <= 73728
    if (sel < 2) {
        // add bias in regs, stage with d-permuted rows, then vectorized copy-out
        #pragma unroll
        for (int mi = 0; mi < 2; mi++) {
            const int m0 = wm * 32 + mi * 16;
            const float bv0 = bias[o0 + m0 + g];
            const float bv1 = bias[o0 + m0 + g + 8];
            const int mp0 = m0 + perm8(g), mp1 = m0 + 8 + perm8(g);
            #pragma unroll
            for (int nf = 0; nf < 8; nf++) {
                const int nn = wn * 64 + nf * 8 + t4 * 2;
                Cs[(nn)     * 132 + mp0] = c[mi][nf][0] + bv0;
                Cs[(nn + 1) * 132 + mp0] = c[mi][nf][1] + bv0;
                Cs[(nn)     * 132 + mp1] = c[mi][nf][2] + bv1;
                Cs[(nn + 1) * 132 + mp1] = c[mi][nf][3] + bv1;
            }
        }
        __syncthreads();
        float* dstbase = (sel == 0) ? g_q : g_k;
        #pragma unroll
        for (int it = 0; it < 16; it++) {
            const int i = tid + it * 256;
            const int nl = i >> 5, m4 = i & 31;
            const float4 cv = *(const float4*)&Cs[nl * 132 + m4 * 4];
            const int o = o0 + m4 * 4;
            const int h = o >> 6, d = o & 63;
            *(float4*)&dstbase[(((size_t)b * NH_ + h) * NTOK_ + n0 + nl) * FH_ + d] = cv;
        }
    } else {
        // V: n-permuted scalar stores to [b][h][d][n-perm]
        #pragma unroll
        for (int mi = 0; mi < 2; mi++) {
            #pragma unroll
            for (int half = 0; half < 2; half++) {
                const int m = wm * 32 + mi * 16 + g + half * 8;
                const int o = o0 + m;
                const int h = o >> 6, d = o & 63;
                const float bval = bias[o];
                float* dst = g_v + (((size_t)b * NH_ + h) * FH_ + d) * NTOK_ + n0;
                #pragma unroll
                for (int nf = 0; nf < 8; nf++) {
                    const int nn = wn * 64 + nf * 8 + t4 * 2;
                    const int s0 = (nn & ~7) | perm8(nn & 7);
                    const int s1 = (nn & ~7) | perm8((nn + 1) & 7);
                    dst[s0] = c[mi][nf][half * 2] + bval;
                    dst[s1] = c[mi][nf][half * 2 + 1] + bval;
                }
            }
        }
    }
}

// ---------------------------------------------------------------------------
// Kernel 2: attention. 8 warps, warp = 16 q rows, Q frags in regs,
// all fragment pair-loads vectorized via permuted layouts.
#define VP 68
__global__ __launch_bounds__(256, 2) void attn_kernel() {
    extern __shared__ uint32_t sm[];
    uint32_t* Ks = sm;
    uint32_t* Vs = Ks + 64 * VP;
    float*    Ps = (float*)(Vs + 64 * VP);
    const uint32_t sb = smem_u32(sm);
    const uint32_t KsB = sb, VsB = sb + 64 * VP * 4;

    const int tid = threadIdx.x;
    const int warp = tid >> 5, lane = tid & 31;
    const int g = lane >> 2, t4 = lane & 3;
    const int m0 = warp * 16;
    const int qt = blockIdx.x, h = blockIdx.y, b = blockIdx.z;
    const size_t hb = (size_t)(b * NH_ + h);
    const float* qsrc = g_q + hb * NTOK_ * FH_ + (size_t)qt * 128 * FH_;
    const float* ksrc = g_k + hb * NTOK_ * FH_;
    const float* vsrc = g_v + hb * FH_ * NTOK_;

    // Q fragments (d-permuted global -> LDG.64 pairs)
    uint32_t qf[8][4];
    {
        const uint2* q0 = (const uint2*)(qsrc + (size_t)(m0 + g) * FH_);
        const uint2* q1 = (const uint2*)(qsrc + (size_t)(m0 + g + 8) * FH_);
        #pragma unroll
        for (int ks = 0; ks < 8; ks++) {
            const uint2 u0 = q0[ks * 4 + t4];
            const uint2 u1 = q1[ks * 4 + t4];
            qf[ks][0] = u0.x; qf[ks][1] = u1.x; qf[ks][2] = u0.y; qf[ks][3] = u1.y;
        }
    }

    auto loadK = [&](int c0) {
        #pragma unroll
        for (int it = 0; it < 4; it++) {
            const int i = tid + it * 256;
            const int r = i >> 4, c4 = i & 15;
            cp16(KsB + (uint32_t)(r * VP + c4 * 4) * 4, ksrc + (size_t)(c0 + r) * FH_ + c4 * 4);
        }
    };
    auto loadV = [&](int c0) {
        #pragma unroll
        for (int it = 0; it < 4; it++) {
            const int i = tid + it * 256;
            const int r = i >> 4, c4 = i & 15;
            cp16(VsB + (uint32_t)(r * VP + c4 * 4) * 4, vsrc + (size_t)r * NTOK_ + c0 + c4 * 4);
        }
    };

    float oacc[8][4];
    #pragma unroll
    for (int nf = 0; nf < 8; nf++)
        #pragma unroll
        for (int q = 0; q < 4; q++) oacc[nf][q] = 0.f;
    float l0 = 0.f, l1 = 0.f;

    loadK(0); loadV(0); CP_COMMIT();

    for (int ck = 0; ck < 16; ck++) {
        const int c1 = (ck + 1) * 64;
        CP_WAIT(0);
        __syncthreads();

        // S = Q K^T : warp tile 16q x 64key; b-frag pairs via LDS.64
        float sc[8][4];
        #pragma unroll
        for (int nf = 0; nf < 8; nf++)
            #pragma unroll
            for (int q = 0; q < 4; q++) sc[nf][q] = 0.f;
        #pragma unroll
        for (int ks = 0; ks < 8; ks++) {
            const int k0 = ks * 8 + 2 * t4;
            #pragma unroll
            for (int nf = 0; nf < 8; nf++) {
                const int nr = nf * 8 + g;
                const uint2 vb = *(const uint2*)&Ks[nr * VP + k0];
                mma8(sc[nf], qf[ks], vb.x, vb.y);
            }
        }
        __syncthreads();
        if (ck < 15) { loadK(c1); CP_COMMIT(); }

        // exp + register row sums + P store (j-permuted scatter)
        float s0 = 0.f, s1 = 0.f;
        const int sp0 = perm8(t4 * 2), sp1 = perm8(t4 * 2 + 1);
        #pragma unroll
        for (int nf = 0; nf < 8; nf++) {
            #pragma unroll
            for (int q = 0; q < 4; q++) sc[nf][q] = __expf(sc[nf][q] * 0.125f);
            s0 += sc[nf][0] + sc[nf][1];
            s1 += sc[nf][2] + sc[nf][3];
            const int jb = nf * 8;
            Ps[(m0 + g)     * VP + jb + sp0] = sc[nf][0];
            Ps[(m0 + g)     * VP + jb + sp1] = sc[nf][1];
            Ps[(m0 + g + 8) * VP + jb + sp0] = sc[nf][2];
            Ps[(m0 + g + 8) * VP + jb + sp1] = sc[nf][3];
        }
        s0 += __shfl_xor_sync(0xffffffffu, s0, 1);
        s0 += __shfl_xor_sync(0xffffffffu, s0, 2);
        s1 += __shfl_xor_sync(0xffffffffu, s1, 1);
        s1 += __shfl_xor_sync(0xffffffffu, s1, 2);
        l0 += s0; l1 += s1;
        __syncwarp();

        // O += P V^T : pa pairs via LDS.64, Vs b-frag pairs via LDS.64
        const uint32_t* Pu = (const uint32_t*)Ps;
        #pragma unroll
        for (int ks = 0; ks < 8; ks++) {
            const int k0 = ks * 8 + 2 * t4;
            const uint2 p0 = *(const uint2*)&Pu[(m0 + g)     * VP + k0];
            const uint2 p1 = *(const uint2*)&Pu[(m0 + g + 8) * VP + k0];
            uint32_t pa[4] = { p0.x, p1.x, p0.y, p1.y };
            #pragma unroll
            for (int nf = 0; nf < 8; nf++) {
                const int nr = nf * 8 + g;
                const uint2 vb = *(const uint2*)&Vs[nr * VP + k0];
                mma8(oacc[nf], pa, vb.x, vb.y);
            }
        }
        __syncthreads();
        if (ck < 15) { loadV(c1); CP_COMMIT(); }
    }

    // normalize + write g_o[b][n][COUT-perm]
    const float inv0 = 1.f / l0, inv1 = 1.f / l1;
    float* d0 = g_o + ((size_t)b * NTOK_ + qt * 128 + m0 + g) * COUT_ + h * FH_;
    float* d1 = d0 + 8 * COUT_;
    #pragma unroll
    for (int nf = 0; nf < 8; nf++) {
        const int dd = nf * 8 + t4 * 2;
        const int s0 = (dd & ~7) | perm8(dd & 7);
        const int s1 = (dd & ~7) | perm8((dd + 1) & 7);
        d0[s0] = oacc[nf][0] * inv0;
        d0[s1] = oacc[nf][1] * inv0;
        d1[s0] = oacc[nf][2] * inv1;
        d1[s1] = oacc[nf][3] * inv1;
    }
}

// ---------------------------------------------------------------------------
// Kernel 3: output projection + bias + residual. 128x128 tiles, K=512.
__global__ __launch_bounds__(256, 2) void oproj_gemm(
    const float* __restrict__ x, const float* __restrict__ bo, float* __restrict__ out)
{
    extern __shared__ uint32_t sm[];
    const int TSZ = 128 * KP;
    const uint32_t sb = smem_u32(sm);

    const int tid = threadIdx.x;
    const int warp = tid >> 5, lane = tid & 31;
    const int g = lane >> 2, t4 = lane & 3;
    const int wm = warp & 3, wn = warp >> 2;
    const int nt = blockIdx.x, mt = blockIdx.y, b = blockIdx.z;
    const int o0 = mt * 128, n0 = nt * 128;
    const float* asrc = g_wo + (size_t)o0 * COUT_;
    const float* bsrc = g_o + ((size_t)b * NTOK_ + n0) * COUT_;

    auto loadAB = [&](int kc, int buf) {
        const uint32_t abase = sb + (uint32_t)(buf * 2 * TSZ) * 4;
        const uint32_t bbase = abase + (uint32_t)TSZ * 4;
        #pragma unroll
        for (int it = 0; it < 4; it++) {
            const int i = tid + it * 256;
            const int r = i >> 3, c4 = i & 7;
            cp16(abase + (uint32_t)(r * KP + c4 * 4) * 4, asrc + (size_t)r * COUT_ + kc * 32 + c4 * 4);
            cp16(bbase + (uint32_t)(r * KP + c4 * 4) * 4, bsrc + (size_t)r * COUT_ + kc * 32 + c4 * 4);
        }
    };

    float c[2][8][4];
    #pragma unroll
    for (int mi = 0; mi < 2; mi++)
        #pragma unroll
        for (int nf = 0; nf < 8; nf++)
            #pragma unroll
            for (int q = 0; q < 4; q++) c[mi][nf][q] = 0.f;

    loadAB(0, 0); CP_COMMIT();

    int buf = 0;
    for (int kc = 0; kc < 16; kc++) {
        if (kc + 1 < 16) { loadAB(kc + 1, buf ^ 1); CP_COMMIT(); CP_WAIT(1); }
        else CP_WAIT(0);
        __syncthreads();
        const uint32_t* A  = sm + buf * 2 * TSZ;
        const uint32_t* Bt = A + TSZ;
        #pragma unroll
        for (int ks = 0; ks < 4; ks++) {
            const int k0 = ks * 8 + 2 * t4;
            uint32_t a[2][4];
            #pragma unroll
            for (int mi = 0; mi < 2; mi++) {
                const int m0 = wm * 32 + mi * 16;
                const uint2 va0 = *(const uint2*)&A[(m0 + g)     * KP + k0];
                const uint2 va1 = *(const uint2*)&A[(m0 + g + 8) * KP + k0];
                a[mi][0] = va0.x; a[mi][1] = va1.x; a[mi][2] = va0.y; a[mi][3] = va1.y;
            }
            #pragma unroll
            for (int nf = 0; nf < 8; nf++) {
                const int nr = wn * 64 + nf * 8 + g;
                const uint2 vb = *(const uint2*)&Bt[nr * KP + k0];
                mma8(c[0][nf], a[0], vb.x, vb.y);
                mma8(c[1][nf], a[1], vb.x, vb.y);
            }
        }
        __syncthreads();
        buf ^= 1;
    }

    #pragma unroll
    for (int mi = 0; mi < 2; mi++) {
        #pragma unroll
        for (int half = 0; half < 2; half++) {
            const int m = o0 + wm * 32 + mi * 16 + g + half * 8;
            const float bval = bo[m];
            const float* xr = x + ((size_t)b * FIN_ + m) * NTOK_ + n0;
            float* outr = out + ((size_t)b * FIN_ + m) * NTOK_ + n0;
            #pragma unroll
            for (int nf = 0; nf < 8; nf++) {
                const int nn = wn * 64 + nf * 8 + t4 * 2;
                const float2 xv = *(const float2*)&xr[nn];
                *(float2*)&outr[nn] = make_float2(xv.x + bval + c[mi][nf][half * 2],
                                                  xv.y + bval + c[mi][nf][half * 2 + 1]);
            }
        }
    }
}

// ---------------------------------------------------------------------------
extern "C" void kernel_launch(void* const* d_in, const int* in_sizes, int n_in,
                              void* d_out, int out_size)
{
    const float* x  = (const float*)d_in[0];
    const float* wq = (const float*)d_in[1];
    const float* bq = (const float*)d_in[2];
    const float* wk = (const float*)d_in[3];
    const float* bk = (const float*)d_in[4];
    const float* wv = (const float*)d_in[5];
    const float* bv = (const float*)d_in[6];
    const float* wo = (const float*)d_in[7];
    const float* bo = (const float*)d_in[8];
    float* out = (float*)d_out;

    const int gemm_smem = 4 * 128 * KP * 4;                 // 73728
    const int attn_smem = (64 * VP * 2 + 128 * VP) * 4;     // 69632
    cudaFuncSetAttribute(qkv_gemm,    cudaFuncAttributeMaxDynamicSharedMemorySize, gemm_smem);
    cudaFuncSetAttribute(oproj_gemm,  cudaFuncAttributeMaxDynamicSharedMemorySize, gemm_smem);
    cudaFuncSetAttribute(attn_kernel, cudaFuncAttributeMaxDynamicSharedMemorySize, attn_smem);

    prep_kernel<<<dim3(32, 16), 256>>>(x);
    pack_w<<<(3 * COUT_ * CPAD_) / 256, 256>>>(wq, wk, wv);
    pack_wo<<<(FIN_ * COUT_) / 256, 256>>>(wo);
    qkv_gemm<<<dim3(8, 12, 16), 256, gemm_smem>>>(bq, bk, bv);
    attn_kernel<<<dim3(8, NH_, B_), 256, attn_smem>>>();
    oproj_gemm<<<dim3(8, 2, 16), 256, gemm_smem>>>(x, bo, out);
}

// round 6
// speedup vs baseline: 2.4330x; 2.4330x over previous
#include <cuda_runtime.h>
#include <cuda_bf16.h>
#include <cstdint>

#define B_    16
#define FIN_  256
#define NTOK_ 1024
#define NH_   8
#define FH_   64
#define CIN_  258
#define CPAD_ 288
#define COUT_ 512

typedef __nv_bfloat16 bf16;

// ---------------------------------------------------------------------------
// Scratch (static device arrays; no allocation allowed) — all bf16
__device__ bf16 g_t[B_ * NTOK_ * CPAD_];          // [b][n][c] padded to 288
__device__ bf16 g_w[3 * COUT_ * CPAD_];           // packed qkv weights
__device__ bf16 g_wo[FIN_ * COUT_];               // wo
__device__ bf16 g_q[B_ * NH_ * NTOK_ * FH_];      // [b][h][n][d]
__device__ bf16 g_k[B_ * NH_ * NTOK_ * FH_];      // [b][h][n][d]
__device__ bf16 g_v[B_ * NH_ * FH_ * NTOK_];      // [b][h][d][n]
__device__ bf16 g_o[B_ * NTOK_ * COUT_];          // [b][n][h*64+d]

// ---------------------------------------------------------------------------
__device__ __forceinline__ uint32_t smem_u32(const void* p) {
    uint32_t a;
    asm("{ .reg .u64 t; cvta.to.shared.u64 t, %1; cvt.u32.u64 %0, t; }" : "=r"(a) : "l"(p));
    return a;
}
__device__ __forceinline__ void cp16(uint32_t sdst, const void* gsrc) {
    asm volatile("cp.async.cg.shared.global [%0], [%1], 16;" :: "r"(sdst), "l"(gsrc));
}
#define CP_COMMIT() asm volatile("cp.async.commit_group;" ::: "memory")
#define CP_WAIT(n)  asm volatile("cp.async.wait_group %0;" :: "n"(n) : "memory")

// pack two fp32 -> bf16x2 word (lo in low half)
__device__ __forceinline__ uint32_t pack2(float lo, float hi) {
    uint32_t r;
    asm("cvt.rn.bf16x2.f32 %0, %1, %2;" : "=r"(r) : "f"(hi), "f"(lo));
    return r;
}

// D += A*B, m16n8k16 bf16, fp32 accum. A row-major 16x16, B [n][k] (col-major).
__device__ __forceinline__ void mma16(float c[4], const uint32_t a[4], uint32_t b0, uint32_t b1) {
    asm volatile(
        "mma.sync.aligned.m16n8k16.row.col.f32.bf16.bf16.f32 "
        "{%0,%1,%2,%3}, {%4,%5,%6,%7}, {%8,%9}, {%0,%1,%2,%3};"
        : "+f"(c[0]), "+f"(c[1]), "+f"(c[2]), "+f"(c[3])
        : "r"(a[0]), "r"(a[1]), "r"(a[2]), "r"(a[3]), "r"(b0), "r"(b1));
}

// ---------------------------------------------------------------------------
// Kernel 0a: t_T[b][n][c] = concat(x, gy, gx) -> bf16, zero-padded to 288.
__global__ __launch_bounds__(256) void prep_kernel(const float* __restrict__ x) {
    __shared__ float tile[32][33];
    const int nt = blockIdx.x, b = blockIdx.y;
    const int tx = threadIdx.x & 31, ty = threadIdx.x >> 5;
    const int n0 = nt * 32;
    for (int c0 = 0; c0 < CPAD_; c0 += 32) {
        for (int ci = ty; ci < 32; ci += 8) {
            const int c = c0 + ci, n = n0 + tx;
            float v = 0.f;
            if (c < FIN_)           v = x[((size_t)b * FIN_ + c) * NTOK_ + n];
            else if (c == FIN_)     v = -1.f + (2.f / 31.f) * (float)(n >> 5);
            else if (c == FIN_ + 1) v = -1.f + (2.f / 31.f) * (float)(n & 31);
            tile[ci][tx] = v;
        }
        __syncthreads();
        for (int ni = ty; ni < 32; ni += 8)
            g_t[((size_t)b * NTOK_ + n0 + ni) * CPAD_ + c0 + tx] =
                __float2bfloat16_rn(tile[tx][ni]);
        __syncthreads();
    }
}

// Kernel 0b: pack q,k,v weights -> bf16 [1536][288], zero-padded.
__global__ __launch_bounds__(256) void pack_w(
    const float* __restrict__ wq, const float* __restrict__ wk, const float* __restrict__ wv)
{
    const int i = blockIdx.x * 256 + threadIdx.x;
    const int r = i / CPAD_, c = i - r * CPAD_;
    const int sel = r >> 9, o = r & 511;
    const float* w = (sel == 0) ? wq : ((sel == 1) ? wk : wv);
    g_w[i] = __float2bfloat16_rn((c < CIN_) ? w[o * CIN_ + c] : 0.f);
}

// Kernel 0c: pack wo -> bf16 [256][512].
__global__ __launch_bounds__(256) void pack_wo(const float* __restrict__ wo) {
    const int i = blockIdx.x * 256 + threadIdx.x;
    g_wo[i] = __float2bfloat16_rn(wo[i]);
}

// ---------------------------------------------------------------------------
// GEMM: CTA 128x128, 8 warps (4m x 2n), warp 32x64, K-chunks 32 (2 k16 steps),
// cp.async double-buffered. Smem row pitch 40 bf16 (80B, conflict-free).
#define AP 20        // words (uint32) per smem row
#define TSZB (128 * 80)
__global__ __launch_bounds__(256, 2) void qkv_gemm(
    const float* __restrict__ bq, const float* __restrict__ bk, const float* __restrict__ bv)
{
    extern __shared__ uint32_t sm[];
    const uint32_t sb = smem_u32(sm);

    const int tid = threadIdx.x;
    const int warp = tid >> 5, lane = tid & 31;
    const int g = lane >> 2, t4 = lane & 3;
    const int wm = warp & 3, wn = warp >> 2;
    const int nt = blockIdx.x, mt = blockIdx.y, b = blockIdx.z;
    const int sel = mt >> 2;
    const int o0 = (mt & 3) * 128;
    const int n0 = nt * 128;
    const bf16* wsrc = g_w + (size_t)(sel * COUT_ + o0) * CPAD_;
    const bf16* bsrc = g_t + ((size_t)b * NTOK_ + n0) * CPAD_;
    const float* bias = (sel == 0) ? bq : ((sel == 1) ? bk : bv);

    auto loadAB = [&](int kc, int buf) {
        const uint32_t ab = sb + (uint32_t)(buf * 2 * TSZB);
        const uint32_t bb = ab + TSZB;
        #pragma unroll
        for (int it = 0; it < 2; it++) {
            const int i = tid + it * 256;
            const int r = i >> 2, c4 = i & 3;
            cp16(ab + (uint32_t)(r * 80 + c4 * 16), wsrc + (size_t)r * CPAD_ + kc * 32 + c4 * 8);
            cp16(bb + (uint32_t)(r * 80 + c4 * 16), bsrc + (size_t)r * CPAD_ + kc * 32 + c4 * 8);
        }
    };

    float c[2][8][4];
    #pragma unroll
    for (int mi = 0; mi < 2; mi++)
        #pragma unroll
        for (int nf = 0; nf < 8; nf++)
            #pragma unroll
            for (int q = 0; q < 4; q++) c[mi][nf][q] = 0.f;

    loadAB(0, 0); CP_COMMIT();

    const int NK = CPAD_ / 32;  // 9
    int buf = 0;
    for (int kc = 0; kc < NK; kc++) {
        if (kc + 1 < NK) { loadAB(kc + 1, buf ^ 1); CP_COMMIT(); CP_WAIT(1); }
        else CP_WAIT(0);
        __syncthreads();
        const uint32_t* A  = sm + buf * 2 * (TSZB / 4);
        const uint32_t* Bt = A + TSZB / 4;
        #pragma unroll
        for (int s = 0; s < 2; s++) {
            const int k0 = s * 8 + t4;
            uint32_t a[2][4];
            #pragma unroll
            for (int mi = 0; mi < 2; mi++) {
                const int m0 = wm * 32 + mi * 16;
                a[mi][0] = A[(m0 + g)     * AP + k0];
                a[mi][1] = A[(m0 + g + 8) * AP + k0];
                a[mi][2] = A[(m0 + g)     * AP + k0 + 4];
                a[mi][3] = A[(m0 + g + 8) * AP + k0 + 4];
            }
            #pragma unroll
            for (int nf = 0; nf < 8; nf++) {
                const int nr = wn * 64 + nf * 8 + g;
                const uint32_t b0 = Bt[nr * AP + k0];
                const uint32_t b1 = Bt[nr * AP + k0 + 4];
                mma16(c[0][nf], a[0], b0, b1);
                mma16(c[1][nf], a[1], b0, b1);
            }
        }
        __syncthreads();
        buf ^= 1;
    }

    float* Cs = (float*)sm;   // staging reuse: 128*132*4 = 67584
    if (sel < 2) {
        #pragma unroll
        for (int mi = 0; mi < 2; mi++) {
            const int m0 = wm * 32 + mi * 16;
            const float bv0 = bias[o0 + m0 + g];
            const float bv1 = bias[o0 + m0 + g + 8];
            #pragma unroll
            for (int nf = 0; nf < 8; nf++) {
                const int nn = wn * 64 + nf * 8 + t4 * 2;
                Cs[(nn)     * 132 + m0 + g]     = c[mi][nf][0] + bv0;
                Cs[(nn + 1) * 132 + m0 + g]     = c[mi][nf][1] + bv0;
                Cs[(nn)     * 132 + m0 + g + 8] = c[mi][nf][2] + bv1;
                Cs[(nn + 1) * 132 + m0 + g + 8] = c[mi][nf][3] + bv1;
            }
        }
        __syncthreads();
        bf16* dstbase = (sel == 0) ? g_q : g_k;
        #pragma unroll
        for (int it = 0; it < 16; it++) {
            const int i = tid + it * 256;
            const int nl = i >> 5, m4 = i & 31;
            const float4 cv = *(const float4*)&Cs[nl * 132 + m4 * 4];
            const int o = o0 + m4 * 4;
            const int h = o >> 6, d = o & 63;
            uint2 pk = make_uint2(pack2(cv.x, cv.y), pack2(cv.z, cv.w));
            *(uint2*)&dstbase[(((size_t)b * NH_ + h) * NTOK_ + n0 + nl) * FH_ + d] = pk;
        }
    } else {
        #pragma unroll
        for (int mi = 0; mi < 2; mi++) {
            #pragma unroll
            for (int half = 0; half < 2; half++) {
                const int m = wm * 32 + mi * 16 + g + half * 8;
                const int o = o0 + m;
                const int h = o >> 6, d = o & 63;
                const float bval = bias[o];
                bf16* dst = g_v + (((size_t)b * NH_ + h) * FH_ + d) * NTOK_ + n0;
                #pragma unroll
                for (int nf = 0; nf < 8; nf++) {
                    const int nn = wn * 64 + nf * 8 + t4 * 2;
                    *(uint32_t*)&dst[nn] = pack2(c[mi][nf][half * 2] + bval,
                                                 c[mi][nf][half * 2 + 1] + bval);
                }
            }
        }
    }
}

// ---------------------------------------------------------------------------
// Kernel 2: attention (bf16). 8 warps, warp = 16 q rows; Q frags in regs.
// Smem: K 64x72 bf16, V 64x72, P 128x72 -> 36864B total. Pitch 72 bf16 = 36 words.
#define KVP 36       // words per row
__global__ __launch_bounds__(256, 2) void attn_kernel() {
    extern __shared__ uint32_t sm[];
    uint32_t* Ks = sm;                    // 64*36 words = 9216B
    uint32_t* Vs = Ks + 64 * KVP;         // 9216B
    uint32_t* Ps = Vs + 64 * KVP;         // 128*36 words = 18432B
    const uint32_t sb = smem_u32(sm);
    const uint32_t KsB = sb, VsB = sb + 64 * KVP * 4;

    const int tid = threadIdx.x;
    const int warp = tid >> 5, lane = tid & 31;
    const int g = lane >> 2, t4 = lane & 3;
    const int m0 = warp * 16;
    const int qt = blockIdx.x, h = blockIdx.y, b = blockIdx.z;
    const size_t hb = (size_t)(b * NH_ + h);
    const bf16* qsrc = g_q + hb * NTOK_ * FH_ + (size_t)qt * 128 * FH_;
    const bf16* ksrc = g_k + hb * NTOK_ * FH_;
    const bf16* vsrc = g_v + hb * FH_ * NTOK_;

    // Q fragments in registers (4 k16 steps)
    uint32_t qf[4][4];
    {
        const uint32_t* q0 = (const uint32_t*)(qsrc + (size_t)(m0 + g) * FH_);
        const uint32_t* q1 = (const uint32_t*)(qsrc + (size_t)(m0 + g + 8) * FH_);
        #pragma unroll
        for (int s = 0; s < 4; s++) {
            qf[s][0] = q0[s * 8 + t4];
            qf[s][1] = q1[s * 8 + t4];
            qf[s][2] = q0[s * 8 + t4 + 4];
            qf[s][3] = q1[s * 8 + t4 + 4];
        }
    }

    auto loadK = [&](int c0) {
        #pragma unroll
        for (int it = 0; it < 2; it++) {
            const int i = tid + it * 256;
            const int r = i >> 3, c8 = i & 7;
            cp16(KsB + (uint32_t)(r * 144 + c8 * 16), ksrc + (size_t)(c0 + r) * FH_ + c8 * 8);
        }
    };
    auto loadV = [&](int c0) {
        #pragma unroll
        for (int it = 0; it < 2; it++) {
            const int i = tid + it * 256;
            const int r = i >> 3, c8 = i & 7;
            cp16(VsB + (uint32_t)(r * 144 + c8 * 16), vsrc + (size_t)r * NTOK_ + c0 + c8 * 8);
        }
    };

    float oacc[8][4];
    #pragma unroll
    for (int nf = 0; nf < 8; nf++)
        #pragma unroll
        for (int q = 0; q < 4; q++) oacc[nf][q] = 0.f;
    float l0 = 0.f, l1 = 0.f;

    loadK(0); loadV(0); CP_COMMIT();

    for (int ck = 0; ck < 16; ck++) {
        const int c1 = (ck + 1) * 64;
        CP_WAIT(0);
        __syncthreads();

        // S = Q K^T : warp tile 16q x 64key, 4 k16 steps
        float sc[8][4];
        #pragma unroll
        for (int nf = 0; nf < 8; nf++)
            #pragma unroll
            for (int q = 0; q < 4; q++) sc[nf][q] = 0.f;
        #pragma unroll
        for (int s = 0; s < 4; s++) {
            const int k0 = s * 8 + t4;
            #pragma unroll
            for (int nf = 0; nf < 8; nf++) {
                const int nr = nf * 8 + g;
                const uint32_t b0 = Ks[nr * KVP + k0];
                const uint32_t b1 = Ks[nr * KVP + k0 + 4];
                mma16(sc[nf], qf[s], b0, b1);
            }
        }
        __syncthreads();
        if (ck < 15) { loadK(c1); CP_COMMIT(); }

        // exp + register row sums + packed bf16 P store (warp-private rows)
        float s0 = 0.f, s1 = 0.f;
        #pragma unroll
        for (int nf = 0; nf < 8; nf++) {
            #pragma unroll
            for (int q = 0; q < 4; q++) sc[nf][q] = __expf(sc[nf][q] * 0.125f);
            s0 += sc[nf][0] + sc[nf][1];
            s1 += sc[nf][2] + sc[nf][3];
            Ps[(m0 + g)     * KVP + nf * 4 + t4] = pack2(sc[nf][0], sc[nf][1]);
            Ps[(m0 + g + 8) * KVP + nf * 4 + t4] = pack2(sc[nf][2], sc[nf][3]);
        }
        s0 += __shfl_xor_sync(0xffffffffu, s0, 1);
        s0 += __shfl_xor_sync(0xffffffffu, s0, 2);
        s1 += __shfl_xor_sync(0xffffffffu, s1, 1);
        s1 += __shfl_xor_sync(0xffffffffu, s1, 2);
        l0 += s0; l1 += s1;
        __syncwarp();

        // O += P V^T : 4 k16 steps
        #pragma unroll
        for (int s = 0; s < 4; s++) {
            const int k0 = s * 8 + t4;
            uint32_t pa[4];
            pa[0] = Ps[(m0 + g)     * KVP + k0];
            pa[1] = Ps[(m0 + g + 8) * KVP + k0];
            pa[2] = Ps[(m0 + g)     * KVP + k0 + 4];
            pa[3] = Ps[(m0 + g + 8) * KVP + k0 + 4];
            #pragma unroll
            for (int nf = 0; nf < 8; nf++) {
                const int nr = nf * 8 + g;
                const uint32_t b0 = Vs[nr * KVP + k0];
                const uint32_t b1 = Vs[nr * KVP + k0 + 4];
                mma16(oacc[nf], pa, b0, b1);
            }
        }
        __syncthreads();
        if (ck < 15) { loadV(c1); CP_COMMIT(); }
    }

    // normalize + write g_o[b][n][h*64+d] (bf16 pairs)
    const float inv0 = 1.f / l0, inv1 = 1.f / l1;
    bf16* d0 = g_o + ((size_t)b * NTOK_ + qt * 128 + m0 + g) * COUT_ + h * FH_;
    bf16* d1 = d0 + 8 * COUT_;
    #pragma unroll
    for (int nf = 0; nf < 8; nf++) {
        const int dd = nf * 8 + t4 * 2;
        *(uint32_t*)&d0[dd] = pack2(oacc[nf][0] * inv0, oacc[nf][1] * inv0);
        *(uint32_t*)&d1[dd] = pack2(oacc[nf][2] * inv1, oacc[nf][3] * inv1);
    }
}

// ---------------------------------------------------------------------------
// Kernel 3: output projection + bias + residual. bf16 inputs, fp32 out.
__global__ __launch_bounds__(256, 2) void oproj_gemm(
    const float* __restrict__ x, const float* __restrict__ bo, float* __restrict__ out)
{
    extern __shared__ uint32_t sm[];
    const uint32_t sb = smem_u32(sm);

    const int tid = threadIdx.x;
    const int warp = tid >> 5, lane = tid & 31;
    const int g = lane >> 2, t4 = lane & 3;
    const int wm = warp & 3, wn = warp >> 2;
    const int nt = blockIdx.x, mt = blockIdx.y, b = blockIdx.z;
    const int o0 = mt * 128, n0 = nt * 128;
    const bf16* asrc = g_wo + (size_t)o0 * COUT_;
    const bf16* bsrc = g_o + ((size_t)b * NTOK_ + n0) * COUT_;

    auto loadAB = [&](int kc, int buf) {
        const uint32_t ab = sb + (uint32_t)(buf * 2 * TSZB);
        const uint32_t bb = ab + TSZB;
        #pragma unroll
        for (int it = 0; it < 2; it++) {
            const int i = tid + it * 256;
            const int r = i >> 2, c4 = i & 3;
            cp16(ab + (uint32_t)(r * 80 + c4 * 16), asrc + (size_t)r * COUT_ + kc * 32 + c4 * 8);
            cp16(bb + (uint32_t)(r * 80 + c4 * 16), bsrc + (size_t)r * COUT_ + kc * 32 + c4 * 8);
        }
    };

    float c[2][8][4];
    #pragma unroll
    for (int mi = 0; mi < 2; mi++)
        #pragma unroll
        for (int nf = 0; nf < 8; nf++)
            #pragma unroll
            for (int q = 0; q < 4; q++) c[mi][nf][q] = 0.f;

    loadAB(0, 0); CP_COMMIT();

    int buf = 0;
    for (int kc = 0; kc < 16; kc++) {
        if (kc + 1 < 16) { loadAB(kc + 1, buf ^ 1); CP_COMMIT(); CP_WAIT(1); }
        else CP_WAIT(0);
        __syncthreads();
        const uint32_t* A  = sm + buf * 2 * (TSZB / 4);
        const uint32_t* Bt = A + TSZB / 4;
        #pragma unroll
        for (int s = 0; s < 2; s++) {
            const int k0 = s * 8 + t4;
            uint32_t a[2][4];
            #pragma unroll
            for (int mi = 0; mi < 2; mi++) {
                const int m0 = wm * 32 + mi * 16;
                a[mi][0] = A[(m0 + g)     * AP + k0];
                a[mi][1] = A[(m0 + g + 8) * AP + k0];
                a[mi][2] = A[(m0 + g)     * AP + k0 + 4];
                a[mi][3] = A[(m0 + g + 8) * AP + k0 + 4];
            }
            #pragma unroll
            for (int nf = 0; nf < 8; nf++) {
                const int nr = wn * 64 + nf * 8 + g;
                const uint32_t b0 = Bt[nr * AP + k0];
                const uint32_t b1 = Bt[nr * AP + k0 + 4];
                mma16(c[0][nf], a[0], b0, b1);
                mma16(c[1][nf], a[1], b0, b1);
            }
        }
        __syncthreads();
        buf ^= 1;
    }

    #pragma unroll
    for (int mi = 0; mi < 2; mi++) {
        #pragma unroll
        for (int half = 0; half < 2; half++) {
            const int m = o0 + wm * 32 + mi * 16 + g + half * 8;
            const float bval = bo[m];
            const float* xr = x + ((size_t)b * FIN_ + m) * NTOK_ + n0;
            float* outr = out + ((size_t)b * FIN_ + m) * NTOK_ + n0;
            #pragma unroll
            for (int nf = 0; nf < 8; nf++) {
                const int nn = wn * 64 + nf * 8 + t4 * 2;
                const float2 xv = *(const float2*)&xr[nn];
                *(float2*)&outr[nn] = make_float2(xv.x + bval + c[mi][nf][half * 2],
                                                  xv.y + bval + c[mi][nf][half * 2 + 1]);
            }
        }
    }
}

// ---------------------------------------------------------------------------
extern "C" void kernel_launch(void* const* d_in, const int* in_sizes, int n_in,
                              void* d_out, int out_size)
{
    const float* x  = (const float*)d_in[0];
    const float* wq = (const float*)d_in[1];
    const float* bq = (const float*)d_in[2];
    const float* wk = (const float*)d_in[3];
    const float* bk = (const float*)d_in[4];
    const float* wv = (const float*)d_in[5];
    const float* bv = (const float*)d_in[6];
    const float* wo = (const float*)d_in[7];
    const float* bo = (const float*)d_in[8];
    float* out = (float*)d_out;

    const int qkv_smem  = 128 * 132 * 4;            // 67584 (tiles 40960, staging 67584)
    const int oproj_smem = 4 * TSZB;                // 40960
    const int attn_smem = (64 * KVP * 2 + 128 * KVP) * 4;  // 36864
    cudaFuncSetAttribute(qkv_gemm,    cudaFuncAttributeMaxDynamicSharedMemorySize, qkv_smem);
    cudaFuncSetAttribute(oproj_gemm,  cudaFuncAttributeMaxDynamicSharedMemorySize, oproj_smem);
    cudaFuncSetAttribute(attn_kernel, cudaFuncAttributeMaxDynamicSharedMemorySize, attn_smem);

    prep_kernel<<<dim3(32, 16), 256>>>(x);
    pack_w<<<(3 * COUT_ * CPAD_) / 256, 256>>>(wq, wk, wv);
    pack_wo<<<(FIN_ * COUT_) / 256, 256>>>(wo);
    qkv_gemm<<<dim3(8, 12, 16), 256, qkv_smem>>>(bq, bk, bv);
    attn_kernel<<<dim3(8, NH_, B_), 256, attn_smem>>>();
    oproj_gemm<<<dim3(8, 2, 16), 256, oproj_smem>>>(x, bo, out);
}

// round 7
// speedup vs baseline: 2.5400x; 1.0440x over previous
#include <cuda_runtime.h>
#include <cuda_bf16.h>
#include <cstdint>

#define B_    16
#define FIN_  256
#define NTOK_ 1024
#define NH_   8
#define FH_   64
#define CIN_  258
#define CPAD_ 288
#define COUT_ 512

typedef __nv_bfloat16 bf16;

// ---------------------------------------------------------------------------
// Scratch (static device arrays; no allocation allowed) — all bf16
__device__ bf16 g_t[B_ * NTOK_ * CPAD_];          // [b][n][c] padded to 288
__device__ bf16 g_w[3 * COUT_ * CPAD_];           // packed qkv weights
__device__ bf16 g_wo[FIN_ * COUT_];               // wo
__device__ bf16 g_q[B_ * NH_ * NTOK_ * FH_];      // [b][h][n][d]
__device__ bf16 g_k[B_ * NH_ * NTOK_ * FH_];      // [b][h][n][d]
__device__ bf16 g_v[B_ * NH_ * FH_ * NTOK_];      // [b][h][d][n]
__device__ bf16 g_o[B_ * NTOK_ * COUT_];          // [b][n][h*64+d]

// ---------------------------------------------------------------------------
__device__ __forceinline__ uint32_t smem_u32(const void* p) {
    uint32_t a;
    asm("{ .reg .u64 t; cvta.to.shared.u64 t, %1; cvt.u32.u64 %0, t; }" : "=r"(a) : "l"(p));
    return a;
}
__device__ __forceinline__ void cp16(uint32_t sdst, const void* gsrc) {
    asm volatile("cp.async.cg.shared.global [%0], [%1], 16;" :: "r"(sdst), "l"(gsrc));
}
#define CP_COMMIT() asm volatile("cp.async.commit_group;" ::: "memory")
#define CP_WAIT(n)  asm volatile("cp.async.wait_group %0;" :: "n"(n) : "memory")

__device__ __forceinline__ uint32_t pack2(float lo, float hi) {
    uint32_t r;
    asm("cvt.rn.bf16x2.f32 %0, %1, %2;" : "=r"(r) : "f"(hi), "f"(lo));
    return r;
}
__device__ __forceinline__ void ldsm4(uint32_t r[4], uint32_t addr) {
    asm volatile("ldmatrix.sync.aligned.m8n8.x4.shared.b16 {%0,%1,%2,%3}, [%4];"
        : "=r"(r[0]), "=r"(r[1]), "=r"(r[2]), "=r"(r[3]) : "r"(addr));
}

// D += A*B, m16n8k16 bf16, fp32 accum.
__device__ __forceinline__ void mma16(float c[4], const uint32_t a[4], uint32_t b0, uint32_t b1) {
    asm volatile(
        "mma.sync.aligned.m16n8k16.row.col.f32.bf16.bf16.f32 "
        "{%0,%1,%2,%3}, {%4,%5,%6,%7}, {%8,%9}, {%0,%1,%2,%3};"
        : "+f"(c[0]), "+f"(c[1]), "+f"(c[2]), "+f"(c[3])
        : "r"(a[0]), "r"(a[1]), "r"(a[2]), "r"(a[3]), "r"(b0), "r"(b1));
}

// ---------------------------------------------------------------------------
// Kernel 0a: t_T[b][n][c] = concat(x, gy, gx) -> bf16, zero-padded to 288.
__global__ __launch_bounds__(256) void prep_kernel(const float* __restrict__ x) {
    __shared__ float tile[32][33];
    const int nt = blockIdx.x, b = blockIdx.y;
    const int tx = threadIdx.x & 31, ty = threadIdx.x >> 5;
    const int n0 = nt * 32;
    for (int c0 = 0; c0 < CPAD_; c0 += 32) {
        for (int ci = ty; ci < 32; ci += 8) {
            const int c = c0 + ci, n = n0 + tx;
            float v = 0.f;
            if (c < FIN_)           v = x[((size_t)b * FIN_ + c) * NTOK_ + n];
            else if (c == FIN_)     v = -1.f + (2.f / 31.f) * (float)(n >> 5);
            else if (c == FIN_ + 1) v = -1.f + (2.f / 31.f) * (float)(n & 31);
            tile[ci][tx] = v;
        }
        __syncthreads();
        for (int ni = ty; ni < 32; ni += 8)
            g_t[((size_t)b * NTOK_ + n0 + ni) * CPAD_ + c0 + tx] =
                __float2bfloat16_rn(tile[tx][ni]);
        __syncthreads();
    }
}

// Kernel 0b: pack q,k,v weights -> bf16 [1536][288], zero-padded.
__global__ __launch_bounds__(256) void pack_w(
    const float* __restrict__ wq, const float* __restrict__ wk, const float* __restrict__ wv)
{
    const int i = blockIdx.x * 256 + threadIdx.x;
    const int r = i / CPAD_, c = i - r * CPAD_;
    const int sel = r >> 9, o = r & 511;
    const float* w = (sel == 0) ? wq : ((sel == 1) ? wk : wv);
    g_w[i] = __float2bfloat16_rn((c < CIN_) ? w[o * CIN_ + c] : 0.f);
}

// Kernel 0c: pack wo -> bf16 [256][512].
__global__ __launch_bounds__(256) void pack_wo(const float* __restrict__ wo) {
    const int i = blockIdx.x * 256 + threadIdx.x;
    g_wo[i] = __float2bfloat16_rn(wo[i]);
}

// ---------------------------------------------------------------------------
// GEMM: CTA 128x128, 8 warps (4m x 2n), warp 32x64, K-chunks 32 (2 k16 steps),
// cp.async double-buffered, all fragments via ldmatrix. Row pitch 80B.
#define TSZB (128 * 80)
__global__ __launch_bounds__(256, 2) void qkv_gemm(
    const float* __restrict__ bq, const float* __restrict__ bk, const float* __restrict__ bv)
{
    extern __shared__ uint32_t sm[];
    const uint32_t sb = smem_u32(sm);

    const int tid = threadIdx.x;
    const int warp = tid >> 5, lane = tid & 31;
    const int g = lane >> 2, t4 = lane & 3;
    const int wm = warp & 3, wn = warp >> 2;
    const int nt = blockIdx.x, mt = blockIdx.y, b = blockIdx.z;
    const int sel = mt >> 2;
    const int o0 = (mt & 3) * 128;
    const int n0 = nt * 128;
    const bf16* wsrc = g_w + (size_t)(sel * COUT_ + o0) * CPAD_;
    const bf16* bsrc = g_t + ((size_t)b * NTOK_ + n0) * CPAD_;
    const float* bias = (sel == 0) ? bq : ((sel == 1) ? bk : bv);

    // per-lane ldmatrix offsets (bytes within tile)
    const uint32_t aoff = (uint32_t)((wm * 32 + (lane & 15)) * 80 + (lane >> 4) * 16);
    const uint32_t boff = (uint32_t)((wn * 64 + (lane >> 4) * 8 + (lane & 7)) * 80
                                     + ((lane >> 3) & 1) * 16);

    auto loadAB = [&](int kc, int buf) {
        const uint32_t ab = sb + (uint32_t)(buf * 2 * TSZB);
        const uint32_t bb = ab + TSZB;
        #pragma unroll
        for (int it = 0; it < 2; it++) {
            const int i = tid + it * 256;
            const int r = i >> 2, c4 = i & 3;
            cp16(ab + (uint32_t)(r * 80 + c4 * 16), wsrc + (size_t)r * CPAD_ + kc * 32 + c4 * 8);
            cp16(bb + (uint32_t)(r * 80 + c4 * 16), bsrc + (size_t)r * CPAD_ + kc * 32 + c4 * 8);
        }
    };

    float c[2][8][4];
    #pragma unroll
    for (int mi = 0; mi < 2; mi++)
        #pragma unroll
        for (int nf = 0; nf < 8; nf++)
            #pragma unroll
            for (int q = 0; q < 4; q++) c[mi][nf][q] = 0.f;

    loadAB(0, 0); CP_COMMIT();

    const int NK = CPAD_ / 32;  // 9
    int buf = 0;
    for (int kc = 0; kc < NK; kc++) {
        if (kc + 1 < NK) { loadAB(kc + 1, buf ^ 1); CP_COMMIT(); CP_WAIT(1); }
        else CP_WAIT(0);
        __syncthreads();
        const uint32_t Ab = sb + (uint32_t)(buf * 2 * TSZB);
        const uint32_t Bb = Ab + TSZB;
        #pragma unroll
        for (int s = 0; s < 2; s++) {
            uint32_t a[2][4];
            ldsm4(a[0], Ab + aoff + s * 32);
            ldsm4(a[1], Ab + aoff + 16 * 80 + s * 32);
            #pragma unroll
            for (int nfp = 0; nfp < 4; nfp++) {
                uint32_t bb4[4];
                ldsm4(bb4, Bb + boff + nfp * 16 * 80 + s * 32);
                mma16(c[0][nfp * 2],     a[0], bb4[0], bb4[1]);
                mma16(c[1][nfp * 2],     a[1], bb4[0], bb4[1]);
                mma16(c[0][nfp * 2 + 1], a[0], bb4[2], bb4[3]);
                mma16(c[1][nfp * 2 + 1], a[1], bb4[2], bb4[3]);
            }
        }
        __syncthreads();
        buf ^= 1;
    }

    float* Cs = (float*)sm;   // staging reuse: 128*132*4 = 67584
    if (sel < 2) {
        #pragma unroll
        for (int mi = 0; mi < 2; mi++) {
            const int m0 = wm * 32 + mi * 16;
            const float bv0 = bias[o0 + m0 + g];
            const float bv1 = bias[o0 + m0 + g + 8];
            #pragma unroll
            for (int nf = 0; nf < 8; nf++) {
                const int nn = wn * 64 + nf * 8 + t4 * 2;
                Cs[(nn)     * 132 + m0 + g]     = c[mi][nf][0] + bv0;
                Cs[(nn + 1) * 132 + m0 + g]     = c[mi][nf][1] + bv0;
                Cs[(nn)     * 132 + m0 + g + 8] = c[mi][nf][2] + bv1;
                Cs[(nn + 1) * 132 + m0 + g + 8] = c[mi][nf][3] + bv1;
            }
        }
        __syncthreads();
        bf16* dstbase = (sel == 0) ? g_q : g_k;
        #pragma unroll
        for (int it = 0; it < 16; it++) {
            const int i = tid + it * 256;
            const int nl = i >> 5, m4 = i & 31;
            const float4 cv = *(const float4*)&Cs[nl * 132 + m4 * 4];
            const int o = o0 + m4 * 4;
            const int h = o >> 6, d = o & 63;
            uint2 pk = make_uint2(pack2(cv.x, cv.y), pack2(cv.z, cv.w));
            *(uint2*)&dstbase[(((size_t)b * NH_ + h) * NTOK_ + n0 + nl) * FH_ + d] = pk;
        }
    } else {
        #pragma unroll
        for (int mi = 0; mi < 2; mi++) {
            #pragma unroll
            for (int half = 0; half < 2; half++) {
                const int m = wm * 32 + mi * 16 + g + half * 8;
                const int o = o0 + m;
                const int h = o >> 6, d = o & 63;
                const float bval = bias[o];
                bf16* dst = g_v + (((size_t)b * NH_ + h) * FH_ + d) * NTOK_ + n0;
                #pragma unroll
                for (int nf = 0; nf < 8; nf++) {
                    const int nn = wn * 64 + nf * 8 + t4 * 2;
                    *(uint32_t*)&dst[nn] = pack2(c[mi][nf][half * 2] + bval,
                                                 c[mi][nf][half * 2 + 1] + bval);
                }
            }
        }
    }
}

// ---------------------------------------------------------------------------
// Kernel 2: attention (bf16, ldmatrix). 8 warps, warp = 16 q rows.
// Smem: K 64x72 bf16 (144B pitch), V 64x72, P 128x72 -> 36864B total.
#define KVP 36       // words per row
__global__ __launch_bounds__(256, 2) void attn_kernel() {
    extern __shared__ uint32_t sm[];
    uint32_t* Ps = sm + 2 * 64 * KVP;
    const uint32_t sb = smem_u32(sm);
    const uint32_t KsB = sb, VsB = sb + 64 * KVP * 4, PsB = VsB + 64 * KVP * 4;

    const int tid = threadIdx.x;
    const int warp = tid >> 5, lane = tid & 31;
    const int g = lane >> 2, t4 = lane & 3;
    const int m0 = warp * 16;
    const int qt = blockIdx.x, h = blockIdx.y, b = blockIdx.z;
    const size_t hb = (size_t)(b * NH_ + h);
    const bf16* qsrc = g_q + hb * NTOK_ * FH_ + (size_t)qt * 128 * FH_;
    const bf16* ksrc = g_k + hb * NTOK_ * FH_;
    const bf16* vsrc = g_v + hb * FH_ * NTOK_;

    // ldmatrix per-lane offsets (bytes)
    const uint32_t kvoff = (uint32_t)(((lane >> 4) * 8 + (lane & 7)) * 144
                                      + ((lane >> 3) & 1) * 16);
    const uint32_t poff  = (uint32_t)((m0 + (lane & 15)) * 144 + (lane >> 4) * 16);

    // Q fragments in registers (4 k16 steps)
    uint32_t qf[4][4];
    {
        const uint32_t* q0 = (const uint32_t*)(qsrc + (size_t)(m0 + g) * FH_);
        const uint32_t* q1 = (const uint32_t*)(qsrc + (size_t)(m0 + g + 8) * FH_);
        #pragma unroll
        for (int s = 0; s < 4; s++) {
            qf[s][0] = q0[s * 8 + t4];
            qf[s][1] = q1[s * 8 + t4];
            qf[s][2] = q0[s * 8 + t4 + 4];
            qf[s][3] = q1[s * 8 + t4 + 4];
        }
    }

    auto loadK = [&](int c0) {
        #pragma unroll
        for (int it = 0; it < 2; it++) {
            const int i = tid + it * 256;
            const int r = i >> 3, c8 = i & 7;
            cp16(KsB + (uint32_t)(r * 144 + c8 * 16), ksrc + (size_t)(c0 + r) * FH_ + c8 * 8);
        }
    };
    auto loadV = [&](int c0) {
        #pragma unroll
        for (int it = 0; it < 2; it++) {
            const int i = tid + it * 256;
            const int r = i >> 3, c8 = i & 7;
            cp16(VsB + (uint32_t)(r * 144 + c8 * 16), vsrc + (size_t)r * NTOK_ + c0 + c8 * 8);
        }
    };

    float oacc[8][4];
    #pragma unroll
    for (int nf = 0; nf < 8; nf++)
        #pragma unroll
        for (int q = 0; q < 4; q++) oacc[nf][q] = 0.f;
    float l0 = 0.f, l1 = 0.f;

    loadK(0); loadV(0); CP_COMMIT();

    for (int ck = 0; ck < 16; ck++) {
        const int c1 = (ck + 1) * 64;
        CP_WAIT(0);
        __syncthreads();

        // S = Q K^T : 4 k16 steps, K fragments via ldmatrix
        float sc[8][4];
        #pragma unroll
        for (int nf = 0; nf < 8; nf++)
            #pragma unroll
            for (int q = 0; q < 4; q++) sc[nf][q] = 0.f;
        #pragma unroll
        for (int s = 0; s < 4; s++) {
            #pragma unroll
            for (int nfp = 0; nfp < 4; nfp++) {
                uint32_t bb4[4];
                ldsm4(bb4, KsB + kvoff + nfp * 16 * 144 + s * 32);
                mma16(sc[nfp * 2],     qf[s], bb4[0], bb4[1]);
                mma16(sc[nfp * 2 + 1], qf[s], bb4[2], bb4[3]);
            }
        }
        __syncthreads();
        if (ck < 15) { loadK(c1); CP_COMMIT(); }

        // exp + register row sums + packed bf16 P store (warp-private rows)
        float s0 = 0.f, s1 = 0.f;
        #pragma unroll
        for (int nf = 0; nf < 8; nf++) {
            #pragma unroll
            for (int q = 0; q < 4; q++) sc[nf][q] = __expf(sc[nf][q] * 0.125f);
            s0 += sc[nf][0] + sc[nf][1];
            s1 += sc[nf][2] + sc[nf][3];
            Ps[(m0 + g)     * KVP + nf * 4 + t4] = pack2(sc[nf][0], sc[nf][1]);
            Ps[(m0 + g + 8) * KVP + nf * 4 + t4] = pack2(sc[nf][2], sc[nf][3]);
        }
        s0 += __shfl_xor_sync(0xffffffffu, s0, 1);
        s0 += __shfl_xor_sync(0xffffffffu, s0, 2);
        s1 += __shfl_xor_sync(0xffffffffu, s1, 1);
        s1 += __shfl_xor_sync(0xffffffffu, s1, 2);
        l0 += s0; l1 += s1;
        __syncwarp();

        // O += P V^T : P + V fragments via ldmatrix
        #pragma unroll
        for (int s = 0; s < 4; s++) {
            uint32_t pa[4];
            ldsm4(pa, PsB + poff + s * 32);
            #pragma unroll
            for (int nfp = 0; nfp < 4; nfp++) {
                uint32_t bb4[4];
                ldsm4(bb4, VsB + kvoff + nfp * 16 * 144 + s * 32);
                mma16(oacc[nfp * 2],     pa, bb4[0], bb4[1]);
                mma16(oacc[nfp * 2 + 1], pa, bb4[2], bb4[3]);
            }
        }
        __syncthreads();
        if (ck < 15) { loadV(c1); CP_COMMIT(); }
    }

    // normalize + write g_o[b][n][h*64+d] (bf16 pairs)
    const float inv0 = 1.f / l0, inv1 = 1.f / l1;
    bf16* d0 = g_o + ((size_t)b * NTOK_ + qt * 128 + m0 + g) * COUT_ + h * FH_;
    bf16* d1 = d0 + 8 * COUT_;
    #pragma unroll
    for (int nf = 0; nf < 8; nf++) {
        const int dd = nf * 8 + t4 * 2;
        *(uint32_t*)&d0[dd] = pack2(oacc[nf][0] * inv0, oacc[nf][1] * inv0);
        *(uint32_t*)&d1[dd] = pack2(oacc[nf][2] * inv1, oacc[nf][3] * inv1);
    }
}

// ---------------------------------------------------------------------------
// Kernel 3: output projection + bias + residual. bf16 inputs, fp32 out, ldmatrix.
__global__ __launch_bounds__(256, 2) void oproj_gemm(
    const float* __restrict__ x, const float* __restrict__ bo, float* __restrict__ out)
{
    extern __shared__ uint32_t sm[];
    const uint32_t sb = smem_u32(sm);

    const int tid = threadIdx.x;
    const int warp = tid >> 5, lane = tid & 31;
    const int g = lane >> 2, t4 = lane & 3;
    const int wm = warp & 3, wn = warp >> 2;
    const int nt = blockIdx.x, mt = blockIdx.y, b = blockIdx.z;
    const int o0 = mt * 128, n0 = nt * 128;
    const bf16* asrc = g_wo + (size_t)o0 * COUT_;
    const bf16* bsrc = g_o + ((size_t)b * NTOK_ + n0) * COUT_;

    const uint32_t aoff = (uint32_t)((wm * 32 + (lane & 15)) * 80 + (lane >> 4) * 16);
    const uint32_t boff = (uint32_t)((wn * 64 + (lane >> 4) * 8 + (lane & 7)) * 80
                                     + ((lane >> 3) & 1) * 16);

    auto loadAB = [&](int kc, int buf) {
        const uint32_t ab = sb + (uint32_t)(buf * 2 * TSZB);
        const uint32_t bb = ab + TSZB;
        #pragma unroll
        for (int it = 0; it < 2; it++) {
            const int i = tid + it * 256;
            const int r = i >> 2, c4 = i & 3;
            cp16(ab + (uint32_t)(r * 80 + c4 * 16), asrc + (size_t)r * COUT_ + kc * 32 + c4 * 8);
            cp16(bb + (uint32_t)(r * 80 + c4 * 16), bsrc + (size_t)r * COUT_ + kc * 32 + c4 * 8);
        }
    };

    float c[2][8][4];
    #pragma unroll
    for (int mi = 0; mi < 2; mi++)
        #pragma unroll
        for (int nf = 0; nf < 8; nf++)
            #pragma unroll
            for (int q = 0; q < 4; q++) c[mi][nf][q] = 0.f;

    loadAB(0, 0); CP_COMMIT();

    int buf = 0;
    for (int kc = 0; kc < 16; kc++) {
        if (kc + 1 < 16) { loadAB(kc + 1, buf ^ 1); CP_COMMIT(); CP_WAIT(1); }
        else CP_WAIT(0);
        __syncthreads();
        const uint32_t Ab = sb + (uint32_t)(buf * 2 * TSZB);
        const uint32_t Bb = Ab + TSZB;
        #pragma unroll
        for (int s = 0; s < 2; s++) {
            uint32_t a[2][4];
            ldsm4(a[0], Ab + aoff + s * 32);
            ldsm4(a[1], Ab + aoff + 16 * 80 + s * 32);
            #pragma unroll
            for (int nfp = 0; nfp < 4; nfp++) {
                uint32_t bb4[4];
                ldsm4(bb4, Bb + boff + nfp * 16 * 80 + s * 32);
                mma16(c[0][nfp * 2],     a[0], bb4[0], bb4[1]);
                mma16(c[1][nfp * 2],     a[1], bb4[0], bb4[1]);
                mma16(c[0][nfp * 2 + 1], a[0], bb4[2], bb4[3]);
                mma16(c[1][nfp * 2 + 1], a[1], bb4[2], bb4[3]);
            }
        }
        __syncthreads();
        buf ^= 1;
    }

    #pragma unroll
    for (int mi = 0; mi < 2; mi++) {
        #pragma unroll
        for (int half = 0; half < 2; half++) {
            const int m = o0 + wm * 32 + mi * 16 + g + half * 8;
            const float bval = bo[m];
            const float* xr = x + ((size_t)b * FIN_ + m) * NTOK_ + n0;
            float* outr = out + ((size_t)b * FIN_ + m) * NTOK_ + n0;
            #pragma unroll
            for (int nf = 0; nf < 8; nf++) {
                const int nn = wn * 64 + nf * 8 + t4 * 2;
                const float2 xv = *(const float2*)&xr[nn];
                *(float2*)&outr[nn] = make_float2(xv.x + bval + c[mi][nf][half * 2],
                                                  xv.y + bval + c[mi][nf][half * 2 + 1]);
            }
        }
    }
}

// ---------------------------------------------------------------------------
extern "C" void kernel_launch(void* const* d_in, const int* in_sizes, int n_in,
                              void* d_out, int out_size)
{
    const float* x  = (const float*)d_in[0];
    const float* wq = (const float*)d_in[1];
    const float* bq = (const float*)d_in[2];
    const float* wk = (const float*)d_in[3];
    const float* bk = (const float*)d_in[4];
    const float* wv = (const float*)d_in[5];
    const float* bv = (const float*)d_in[6];
    const float* wo = (const float*)d_in[7];
    const float* bo = (const float*)d_in[8];
    float* out = (float*)d_out;

    const int qkv_smem   = 128 * 132 * 4;                  // 67584 (tiles 40960, staging 67584)
    const int oproj_smem = 4 * TSZB;                       // 40960
    const int attn_smem  = (64 * KVP * 2 + 128 * KVP) * 4; // 36864
    cudaFuncSetAttribute(qkv_gemm,    cudaFuncAttributeMaxDynamicSharedMemorySize, qkv_smem);
    cudaFuncSetAttribute(oproj_gemm,  cudaFuncAttributeMaxDynamicSharedMemorySize, oproj_smem);
    cudaFuncSetAttribute(attn_kernel, cudaFuncAttributeMaxDynamicSharedMemorySize, attn_smem);

    prep_kernel<<<dim3(32, 16), 256>>>(x);
    pack_w<<<(3 * COUT_ * CPAD_) / 256, 256>>>(wq, wk, wv);
    pack_wo<<<(FIN_ * COUT_) / 256, 256>>>(wo);
    qkv_gemm<<<dim3(8, 12, 16), 256, qkv_smem>>>(bq, bk, bv);
    attn_kernel<<<dim3(8, NH_, B_), 256, attn_smem>>>();
    oproj_gemm<<<dim3(8, 2, 16), 256, oproj_smem>>>(x, bo, out);
}

// round 8
// speedup vs baseline: 2.8375x; 1.1171x over previous
#include <cuda_runtime.h>
#include <cuda_bf16.h>
#include <cstdint>

#define B_    16
#define FIN_  256
#define NTOK_ 1024
#define NH_   8
#define FH_   64
#define CIN_  258
#define CPAD_ 288
#define COUT_ 512

typedef __nv_bfloat16 bf16;

// ---------------------------------------------------------------------------
__device__ bf16 g_t[B_ * NTOK_ * CPAD_];          // [b][n][c] padded to 288
__device__ bf16 g_w[3 * COUT_ * CPAD_];           // packed qkv weights
__device__ bf16 g_wo[FIN_ * COUT_];               // wo
__device__ bf16 g_q[B_ * NH_ * NTOK_ * FH_];      // [b][h][n][d]
__device__ bf16 g_k[B_ * NH_ * NTOK_ * FH_];      // [b][h][n][d]
__device__ bf16 g_v[B_ * NH_ * FH_ * NTOK_];      // [b][h][d][n]
__device__ bf16 g_o[B_ * NTOK_ * COUT_];          // [b][n][h*64+d]

// ---------------------------------------------------------------------------
__device__ __forceinline__ uint32_t smem_u32(const void* p) {
    uint32_t a;
    asm("{ .reg .u64 t; cvta.to.shared.u64 t, %1; cvt.u32.u64 %0, t; }" : "=r"(a) : "l"(p));
    return a;
}
__device__ __forceinline__ void cp16(uint32_t sdst, const void* gsrc) {
    asm volatile("cp.async.cg.shared.global [%0], [%1], 16;" :: "r"(sdst), "l"(gsrc));
}
#define CP_COMMIT() asm volatile("cp.async.commit_group;" ::: "memory")
#define CP_WAIT(n)  asm volatile("cp.async.wait_group %0;" :: "n"(n) : "memory")

__device__ __forceinline__ uint32_t pack2(float lo, float hi) {
    uint32_t r;
    asm("cvt.rn.bf16x2.f32 %0, %1, %2;" : "=r"(r) : "f"(hi), "f"(lo));
    return r;
}
__device__ __forceinline__ void ldsm4(uint32_t r[4], uint32_t addr) {
    asm volatile("ldmatrix.sync.aligned.m8n8.x4.shared.b16 {%0,%1,%2,%3}, [%4];"
        : "=r"(r[0]), "=r"(r[1]), "=r"(r[2]), "=r"(r[3]) : "r"(addr));
}
__device__ __forceinline__ void mma16(float c[4], const uint32_t a[4], uint32_t b0, uint32_t b1) {
    asm volatile(
        "mma.sync.aligned.m16n8k16.row.col.f32.bf16.bf16.f32 "
        "{%0,%1,%2,%3}, {%4,%5,%6,%7}, {%8,%9}, {%0,%1,%2,%3};"
        : "+f"(c[0]), "+f"(c[1]), "+f"(c[2]), "+f"(c[3])
        : "r"(a[0]), "r"(a[1]), "r"(a[2]), "r"(a[3]), "r"(b0), "r"(b1));
}

// ---------------------------------------------------------------------------
// Kernel 0 (fused): prep t_T, pack qkv weights, pack wo.
__global__ __launch_bounds__(256) void prep_pack(
    const float* __restrict__ x,
    const float* __restrict__ wq, const float* __restrict__ wk, const float* __restrict__ wv,
    const float* __restrict__ wo)
{
    const int blk = blockIdx.x;
    if (blk < 512) {
        // prep: t_T[b][n][c] = concat(x, gy, gx) -> bf16, padded to 288
        __shared__ float tile[32][33];
        const int nt = blk & 31, b = blk >> 5;
        const int tx = threadIdx.x & 31, ty = threadIdx.x >> 5;
        const int n0 = nt * 32;
        for (int c0 = 0; c0 < CPAD_; c0 += 32) {
            for (int ci = ty; ci < 32; ci += 8) {
                const int c = c0 + ci, n = n0 + tx;
                float v = 0.f;
                if (c < FIN_)           v = x[((size_t)b * FIN_ + c) * NTOK_ + n];
                else if (c == FIN_)     v = -1.f + (2.f / 31.f) * (float)(n >> 5);
                else if (c == FIN_ + 1) v = -1.f + (2.f / 31.f) * (float)(n & 31);
                tile[ci][tx] = v;
            }
            __syncthreads();
            for (int ni = ty; ni < 32; ni += 8)
                g_t[((size_t)b * NTOK_ + n0 + ni) * CPAD_ + c0 + tx] =
                    __float2bfloat16_rn(tile[tx][ni]);
            __syncthreads();
        }
    } else if (blk < 512 + 1728) {
        const int i = (blk - 512) * 256 + threadIdx.x;       // 3*512*288
        const int r = i / CPAD_, c = i - r * CPAD_;
        const int sel = r >> 9, o = r & 511;
        const float* w = (sel == 0) ? wq : ((sel == 1) ? wk : wv);
        g_w[i] = __float2bfloat16_rn((c < CIN_) ? w[o * CIN_ + c] : 0.f);
    } else {
        const int i = (blk - 512 - 1728) * 256 + threadIdx.x; // 256*512
        g_wo[i] = __float2bfloat16_rn(wo[i]);
    }
}

// ---------------------------------------------------------------------------
// GEMM: CTA 128x128, 8 warps (4m x 2n), K-chunks 32 (2 k16 steps),
// 3-stage cp.async pipeline, one __syncthreads per chunk, ldmatrix fragments.
#define TSZB (128 * 80)
__global__ __launch_bounds__(256, 2) void qkv_gemm(
    const float* __restrict__ bq, const float* __restrict__ bk, const float* __restrict__ bv)
{
    extern __shared__ uint32_t sm[];
    const uint32_t sb = smem_u32(sm);

    const int tid = threadIdx.x;
    const int warp = tid >> 5, lane = tid & 31;
    const int g = lane >> 2, t4 = lane & 3;
    const int wm = warp & 3, wn = warp >> 2;
    const int nt = blockIdx.x, mt = blockIdx.y, b = blockIdx.z;
    const int sel = mt >> 2;
    const int o0 = (mt & 3) * 128;
    const int n0 = nt * 128;
    const bf16* wsrc = g_w + (size_t)(sel * COUT_ + o0) * CPAD_;
    const bf16* bsrc = g_t + ((size_t)b * NTOK_ + n0) * CPAD_;
    const float* bias = (sel == 0) ? bq : ((sel == 1) ? bk : bv);

    const uint32_t aoff = (uint32_t)((wm * 32 + (lane & 15)) * 80 + (lane >> 4) * 16);
    const uint32_t boff = (uint32_t)((wn * 64 + (lane >> 4) * 8 + (lane & 7)) * 80
                                     + ((lane >> 3) & 1) * 16);

    auto loadAB = [&](int kc, int st) {
        const uint32_t ab = sb + (uint32_t)(st * 2 * TSZB);
        const uint32_t bb = ab + TSZB;
        #pragma unroll
        for (int it = 0; it < 2; it++) {
            const int i = tid + it * 256;
            const int r = i >> 2, c4 = i & 3;
            cp16(ab + (uint32_t)(r * 80 + c4 * 16), wsrc + (size_t)r * CPAD_ + kc * 32 + c4 * 8);
            cp16(bb + (uint32_t)(r * 80 + c4 * 16), bsrc + (size_t)r * CPAD_ + kc * 32 + c4 * 8);
        }
    };

    float c[2][8][4];
    #pragma unroll
    for (int mi = 0; mi < 2; mi++)
        #pragma unroll
        for (int nf = 0; nf < 8; nf++)
            #pragma unroll
            for (int q = 0; q < 4; q++) c[mi][nf][q] = 0.f;

    loadAB(0, 0); CP_COMMIT();
    loadAB(1, 1); CP_COMMIT();

    const int NK = CPAD_ / 32;  // 9
    for (int kc = 0; kc < NK; kc++) {
        if (kc + 1 < NK) CP_WAIT(1); else CP_WAIT(0);
        __syncthreads();
        if (kc + 2 < NK) { loadAB(kc + 2, (kc + 2) % 3); CP_COMMIT(); }
        const uint32_t Ab = sb + (uint32_t)((kc % 3) * 2 * TSZB);
        const uint32_t Bb = Ab + TSZB;
        #pragma unroll
        for (int s = 0; s < 2; s++) {
            uint32_t a[2][4];
            ldsm4(a[0], Ab + aoff + s * 32);
            ldsm4(a[1], Ab + aoff + 16 * 80 + s * 32);
            #pragma unroll
            for (int nfp = 0; nfp < 4; nfp++) {
                uint32_t bb4[4];
                ldsm4(bb4, Bb + boff + nfp * 16 * 80 + s * 32);
                mma16(c[0][nfp * 2],     a[0], bb4[0], bb4[1]);
                mma16(c[1][nfp * 2],     a[1], bb4[0], bb4[1]);
                mma16(c[0][nfp * 2 + 1], a[0], bb4[2], bb4[3]);
                mma16(c[1][nfp * 2 + 1], a[1], bb4[2], bb4[3]);
            }
        }
    }
    __syncthreads();

    float* Cs = (float*)sm;   // staging reuse: 128*132*4 = 67584
    if (sel < 2) {
        #pragma unroll
        for (int mi = 0; mi < 2; mi++) {
            const int m0 = wm * 32 + mi * 16;
            const float bv0 = bias[o0 + m0 + g];
            const float bv1 = bias[o0 + m0 + g + 8];
            #pragma unroll
            for (int nf = 0; nf < 8; nf++) {
                const int nn = wn * 64 + nf * 8 + t4 * 2;
                Cs[(nn)     * 132 + m0 + g]     = c[mi][nf][0] + bv0;
                Cs[(nn + 1) * 132 + m0 + g]     = c[mi][nf][1] + bv0;
                Cs[(nn)     * 132 + m0 + g + 8] = c[mi][nf][2] + bv1;
                Cs[(nn + 1) * 132 + m0 + g + 8] = c[mi][nf][3] + bv1;
            }
        }
        __syncthreads();
        bf16* dstbase = (sel == 0) ? g_q : g_k;
        #pragma unroll
        for (int it = 0; it < 16; it++) {
            const int i = tid + it * 256;
            const int nl = i >> 5, m4 = i & 31;
            const float4 cv = *(const float4*)&Cs[nl * 132 + m4 * 4];
            const int o = o0 + m4 * 4;
            const int h = o >> 6, d = o & 63;
            uint2 pk = make_uint2(pack2(cv.x, cv.y), pack2(cv.z, cv.w));
            *(uint2*)&dstbase[(((size_t)b * NH_ + h) * NTOK_ + n0 + nl) * FH_ + d] = pk;
        }
    } else {
        #pragma unroll
        for (int mi = 0; mi < 2; mi++) {
            #pragma unroll
            for (int half = 0; half < 2; half++) {
                const int m = wm * 32 + mi * 16 + g + half * 8;
                const int o = o0 + m;
                const int h = o >> 6, d = o & 63;
                const float bval = bias[o];
                bf16* dst = g_v + (((size_t)b * NH_ + h) * FH_ + d) * NTOK_ + n0;
                #pragma unroll
                for (int nf = 0; nf < 8; nf++) {
                    const int nn = wn * 64 + nf * 8 + t4 * 2;
                    *(uint32_t*)&dst[nn] = pack2(c[mi][nf][half * 2] + bval,
                                                 c[mi][nf][half * 2 + 1] + bval);
                }
            }
        }
    }
}

// ---------------------------------------------------------------------------
// Kernel 2: attention. 3-buffer K and V, distance-2 prefetch, ONE barrier/chunk.
// Smem: K 3x9216 + V 3x9216 + P 18432 = 73728.
#define KVP 36         // words per 144B row
#define KVSTG 9216     // bytes per K or V stage
__global__ __launch_bounds__(256, 2) void attn_kernel() {
    extern __shared__ uint32_t sm[];
    uint32_t* Ps = sm + 6 * (KVSTG / 4);
    const uint32_t sb = smem_u32(sm);
    const uint32_t KsB = sb, VsB = sb + 3 * KVSTG, PsB = sb + 6 * KVSTG;

    const int tid = threadIdx.x;
    const int warp = tid >> 5, lane = tid & 31;
    const int g = lane >> 2, t4 = lane & 3;
    const int m0 = warp * 16;
    const int qt = blockIdx.x, h = blockIdx.y, b = blockIdx.z;
    const size_t hb = (size_t)(b * NH_ + h);
    const bf16* qsrc = g_q + hb * NTOK_ * FH_ + (size_t)qt * 128 * FH_;
    const bf16* ksrc = g_k + hb * NTOK_ * FH_;
    const bf16* vsrc = g_v + hb * FH_ * NTOK_;

    const uint32_t kvoff = (uint32_t)(((lane >> 4) * 8 + (lane & 7)) * 144
                                      + ((lane >> 3) & 1) * 16);
    const uint32_t poff  = (uint32_t)((m0 + (lane & 15)) * 144 + (lane >> 4) * 16);

    uint32_t qf[4][4];
    {
        const uint32_t* q0 = (const uint32_t*)(qsrc + (size_t)(m0 + g) * FH_);
        const uint32_t* q1 = (const uint32_t*)(qsrc + (size_t)(m0 + g + 8) * FH_);
        #pragma unroll
        for (int s = 0; s < 4; s++) {
            qf[s][0] = q0[s * 8 + t4];
            qf[s][1] = q1[s * 8 + t4];
            qf[s][2] = q0[s * 8 + t4 + 4];
            qf[s][3] = q1[s * 8 + t4 + 4];
        }
    }

    auto loadKV = [&](int ck, int st) {
        const int c0 = ck * 64;
        #pragma unroll
        for (int it = 0; it < 2; it++) {
            const int i = tid + it * 256;
            const int r = i >> 3, c8 = i & 7;
            cp16(KsB + (uint32_t)(st * KVSTG + r * 144 + c8 * 16),
                 ksrc + (size_t)(c0 + r) * FH_ + c8 * 8);
            cp16(VsB + (uint32_t)(st * KVSTG + r * 144 + c8 * 16),
                 vsrc + (size_t)r * NTOK_ + c0 + c8 * 8);
        }
    };

    float oacc[8][4];
    #pragma unroll
    for (int nf = 0; nf < 8; nf++)
        #pragma unroll
        for (int q = 0; q < 4; q++) oacc[nf][q] = 0.f;
    float l0 = 0.f, l1 = 0.f;

    loadKV(0, 0); CP_COMMIT();
    loadKV(1, 1); CP_COMMIT();

    for (int ck = 0; ck < 16; ck++) {
        if (ck + 1 < 16) CP_WAIT(1); else CP_WAIT(0);
        __syncthreads();
        if (ck + 2 < 16) { loadKV(ck + 2, (ck + 2) % 3); CP_COMMIT(); }
        const uint32_t Kb = KsB + (uint32_t)((ck % 3) * KVSTG);
        const uint32_t Vb = VsB + (uint32_t)((ck % 3) * KVSTG);

        // S = Q K^T
        float sc[8][4];
        #pragma unroll
        for (int nf = 0; nf < 8; nf++)
            #pragma unroll
            for (int q = 0; q < 4; q++) sc[nf][q] = 0.f;
        #pragma unroll
        for (int s = 0; s < 4; s++) {
            #pragma unroll
            for (int nfp = 0; nfp < 4; nfp++) {
                uint32_t bb4[4];
                ldsm4(bb4, Kb + kvoff + nfp * 16 * 144 + s * 32);
                mma16(sc[nfp * 2],     qf[s], bb4[0], bb4[1]);
                mma16(sc[nfp * 2 + 1], qf[s], bb4[2], bb4[3]);
            }
        }

        // exp + row sums + packed bf16 P store (warp-private rows)
        float s0 = 0.f, s1 = 0.f;
        #pragma unroll
        for (int nf = 0; nf < 8; nf++) {
            #pragma unroll
            for (int q = 0; q < 4; q++) sc[nf][q] = __expf(sc[nf][q] * 0.125f);
            s0 += sc[nf][0] + sc[nf][1];
            s1 += sc[nf][2] + sc[nf][3];
            Ps[(m0 + g)     * KVP + nf * 4 + t4] = pack2(sc[nf][0], sc[nf][1]);
            Ps[(m0 + g + 8) * KVP + nf * 4 + t4] = pack2(sc[nf][2], sc[nf][3]);
        }
        s0 += __shfl_xor_sync(0xffffffffu, s0, 1);
        s0 += __shfl_xor_sync(0xffffffffu, s0, 2);
        s1 += __shfl_xor_sync(0xffffffffu, s1, 1);
        s1 += __shfl_xor_sync(0xffffffffu, s1, 2);
        l0 += s0; l1 += s1;
        __syncwarp();

        // O += P V^T
        #pragma unroll
        for (int s = 0; s < 4; s++) {
            uint32_t pa[4];
            ldsm4(pa, PsB + poff + s * 32);
            #pragma unroll
            for (int nfp = 0; nfp < 4; nfp++) {
                uint32_t bb4[4];
                ldsm4(bb4, Vb + kvoff + nfp * 16 * 144 + s * 32);
                mma16(oacc[nfp * 2],     pa, bb4[0], bb4[1]);
                mma16(oacc[nfp * 2 + 1], pa, bb4[2], bb4[3]);
            }
        }
    }

    const float inv0 = 1.f / l0, inv1 = 1.f / l1;
    bf16* d0 = g_o + ((size_t)b * NTOK_ + qt * 128 + m0 + g) * COUT_ + h * FH_;
    bf16* d1 = d0 + 8 * COUT_;
    #pragma unroll
    for (int nf = 0; nf < 8; nf++) {
        const int dd = nf * 8 + t4 * 2;
        *(uint32_t*)&d0[dd] = pack2(oacc[nf][0] * inv0, oacc[nf][1] * inv0);
        *(uint32_t*)&d1[dd] = pack2(oacc[nf][2] * inv1, oacc[nf][3] * inv1);
    }
}

// ---------------------------------------------------------------------------
// Kernel 3: output projection + bias + residual, 3-stage pipeline.
__global__ __launch_bounds__(256, 2) void oproj_gemm(
    const float* __restrict__ x, const float* __restrict__ bo, float* __restrict__ out)
{
    extern __shared__ uint32_t sm[];
    const uint32_t sb = smem_u32(sm);

    const int tid = threadIdx.x;
    const int warp = tid >> 5, lane = tid & 31;
    const int g = lane >> 2, t4 = lane & 3;
    const int wm = warp & 3, wn = warp >> 2;
    const int nt = blockIdx.x, mt = blockIdx.y, b = blockIdx.z;
    const int o0 = mt * 128, n0 = nt * 128;
    const bf16* asrc = g_wo + (size_t)o0 * COUT_;
    const bf16* bsrc = g_o + ((size_t)b * NTOK_ + n0) * COUT_;

    const uint32_t aoff = (uint32_t)((wm * 32 + (lane & 15)) * 80 + (lane >> 4) * 16);
    const uint32_t boff = (uint32_t)((wn * 64 + (lane >> 4) * 8 + (lane & 7)) * 80
                                     + ((lane >> 3) & 1) * 16);

    auto loadAB = [&](int kc, int st) {
        const uint32_t ab = sb + (uint32_t)(st * 2 * TSZB);
        const uint32_t bb = ab + TSZB;
        #pragma unroll
        for (int it = 0; it < 2; it++) {
            const int i = tid + it * 256;
            const int r = i >> 2, c4 = i & 3;
            cp16(ab + (uint32_t)(r * 80 + c4 * 16), asrc + (size_t)r * COUT_ + kc * 32 + c4 * 8);
            cp16(bb + (uint32_t)(r * 80 + c4 * 16), bsrc + (size_t)r * COUT_ + kc * 32 + c4 * 8);
        }
    };

    float c[2][8][4];
    #pragma unroll
    for (int mi = 0; mi < 2; mi++)
        #pragma unroll
        for (int nf = 0; nf < 8; nf++)
            #pragma unroll
            for (int q = 0; q < 4; q++) c[mi][nf][q] = 0.f;

    loadAB(0, 0); CP_COMMIT();
    loadAB(1, 1); CP_COMMIT();

    const int NK = 16;
    for (int kc = 0; kc < NK; kc++) {
        if (kc + 1 < NK) CP_WAIT(1); else CP_WAIT(0);
        __syncthreads();
        if (kc + 2 < NK) { loadAB(kc + 2, (kc + 2) % 3); CP_COMMIT(); }
        const uint32_t Ab = sb + (uint32_t)((kc % 3) * 2 * TSZB);
        const uint32_t Bb = Ab + TSZB;
        #pragma unroll
        for (int s = 0; s < 2; s++) {
            uint32_t a[2][4];
            ldsm4(a[0], Ab + aoff + s * 32);
            ldsm4(a[1], Ab + aoff + 16 * 80 + s * 32);
            #pragma unroll
            for (int nfp = 0; nfp < 4; nfp++) {
                uint32_t bb4[4];
                ldsm4(bb4, Bb + boff + nfp * 16 * 80 + s * 32);
                mma16(c[0][nfp * 2],     a[0], bb4[0], bb4[1]);
                mma16(c[1][nfp * 2],     a[1], bb4[0], bb4[1]);
                mma16(c[0][nfp * 2 + 1], a[0], bb4[2], bb4[3]);
                mma16(c[1][nfp * 2 + 1], a[1], bb4[2], bb4[3]);
            }
        }
    }

    #pragma unroll
    for (int mi = 0; mi < 2; mi++) {
        #pragma unroll
        for (int half = 0; half < 2; half++) {
            const int m = o0 + wm * 32 + mi * 16 + g + half * 8;
            const float bval = bo[m];
            const float* xr = x + ((size_t)b * FIN_ + m) * NTOK_ + n0;
            float* outr = out + ((size_t)b * FIN_ + m) * NTOK_ + n0;
            #pragma unroll
            for (int nf = 0; nf < 8; nf++) {
                const int nn = wn * 64 + nf * 8 + t4 * 2;
                const float2 xv = *(const float2*)&xr[nn];
                *(float2*)&outr[nn] = make_float2(xv.x + bval + c[mi][nf][half * 2],
                                                  xv.y + bval + c[mi][nf][half * 2 + 1]);
            }
        }
    }
}

// ---------------------------------------------------------------------------
extern "C" void kernel_launch(void* const* d_in, const int* in_sizes, int n_in,
                              void* d_out, int out_size)
{
    const float* x  = (const float*)d_in[0];
    const float* wq = (const float*)d_in[1];
    const float* bq = (const float*)d_in[2];
    const float* wk = (const float*)d_in[3];
    const float* bk = (const float*)d_in[4];
    const float* wv = (const float*)d_in[5];
    const float* bv = (const float*)d_in[6];
    const float* wo = (const float*)d_in[7];
    const float* bo = (const float*)d_in[8];
    float* out = (float*)d_out;

    const int qkv_smem   = 128 * 132 * 4;        // 67584 (pipeline 61440, staging 67584)
    const int oproj_smem = 3 * 2 * TSZB;         // 61440
    const int attn_smem  = 6 * KVSTG + 18432;    // 73728
    cudaFuncSetAttribute(qkv_gemm,    cudaFuncAttributeMaxDynamicSharedMemorySize, qkv_smem);
    cudaFuncSetAttribute(oproj_gemm,  cudaFuncAttributeMaxDynamicSharedMemorySize, oproj_smem);
    cudaFuncSetAttribute(attn_kernel, cudaFuncAttributeMaxDynamicSharedMemorySize, attn_smem);

    prep_pack<<<512 + 1728 + 512, 256>>>(x, wq, wk, wv, wo);
    qkv_gemm<<<dim3(8, 12, 16), 256, qkv_smem>>>(bq, bk, bv);
    attn_kernel<<<dim3(8, NH_, B_), 256, attn_smem>>>();
    oproj_gemm<<<dim3(8, 2, 16), 256, oproj_smem>>>(x, bo, out);
}

// round 9
// speedup vs baseline: 3.0955x; 1.0909x over previous
#include <cuda_runtime.h>
#include <cuda_bf16.h>
#include <cstdint>

#define B_    16
#define FIN_  256
#define NTOK_ 1024
#define NH_   8
#define FH_   64
#define CIN_  258
#define CPAD_ 288
#define COUT_ 512

typedef __nv_bfloat16 bf16;

// ---------------------------------------------------------------------------
__device__ bf16 g_t[B_ * NTOK_ * CPAD_];          // [b][n][c] padded to 288
__device__ bf16 g_w[3 * COUT_ * CPAD_];           // packed qkv weights
__device__ bf16 g_wo[FIN_ * COUT_];               // wo
__device__ bf16 g_q[B_ * NH_ * NTOK_ * FH_];      // [b][h][n][d]
__device__ bf16 g_k[B_ * NH_ * NTOK_ * FH_];      // [b][h][n][d]
__device__ bf16 g_v[B_ * NH_ * FH_ * NTOK_];      // [b][h][d][n]
__device__ bf16 g_o[B_ * NTOK_ * COUT_];          // [b][n][h*64+d]

// ---------------------------------------------------------------------------
__device__ __forceinline__ uint32_t smem_u32(const void* p) {
    uint32_t a;
    asm("{ .reg .u64 t; cvta.to.shared.u64 t, %1; cvt.u32.u64 %0, t; }" : "=r"(a) : "l"(p));
    return a;
}
__device__ __forceinline__ void cp16(uint32_t sdst, const void* gsrc) {
    asm volatile("cp.async.cg.shared.global [%0], [%1], 16;" :: "r"(sdst), "l"(gsrc));
}
#define CP_COMMIT() asm volatile("cp.async.commit_group;" ::: "memory")
#define CP_WAIT(n)  asm volatile("cp.async.wait_group %0;" :: "n"(n) : "memory")

__device__ __forceinline__ uint32_t pack2(float lo, float hi) {
    uint32_t r;
    asm("cvt.rn.bf16x2.f32 %0, %1, %2;" : "=r"(r) : "f"(hi), "f"(lo));
    return r;
}
__device__ __forceinline__ uint32_t ex2_bf16x2(uint32_t a) {
    uint32_t r;
    asm("ex2.approx.ftz.bf16x2 %0, %1;" : "=r"(r) : "r"(a));
    return r;
}
__device__ __forceinline__ void ldsm4(uint32_t r[4], uint32_t addr) {
    asm volatile("ldmatrix.sync.aligned.m8n8.x4.shared.b16 {%0,%1,%2,%3}, [%4];"
        : "=r"(r[0]), "=r"(r[1]), "=r"(r[2]), "=r"(r[3]) : "r"(addr));
}
__device__ __forceinline__ void mma16(float c[4], const uint32_t a[4], uint32_t b0, uint32_t b1) {
    asm volatile(
        "mma.sync.aligned.m16n8k16.row.col.f32.bf16.bf16.f32 "
        "{%0,%1,%2,%3}, {%4,%5,%6,%7}, {%8,%9}, {%0,%1,%2,%3};"
        : "+f"(c[0]), "+f"(c[1]), "+f"(c[2]), "+f"(c[3])
        : "r"(a[0]), "r"(a[1]), "r"(a[2]), "r"(a[3]), "r"(b0), "r"(b1));
}

// ---------------------------------------------------------------------------
// Kernel 0 (fused): prep t_T, pack qkv weights, pack wo.
__global__ __launch_bounds__(256) void prep_pack(
    const float* __restrict__ x,
    const float* __restrict__ wq, const float* __restrict__ wk, const float* __restrict__ wv,
    const float* __restrict__ wo)
{
    const int blk = blockIdx.x;
    if (blk < 512) {
        __shared__ float tile[32][33];
        const int nt = blk & 31, b = blk >> 5;
        const int tx = threadIdx.x & 31, ty = threadIdx.x >> 5;
        const int n0 = nt * 32;
        for (int c0 = 0; c0 < CPAD_; c0 += 32) {
            for (int ci = ty; ci < 32; ci += 8) {
                const int c = c0 + ci, n = n0 + tx;
                float v = 0.f;
                if (c < FIN_)           v = x[((size_t)b * FIN_ + c) * NTOK_ + n];
                else if (c == FIN_)     v = -1.f + (2.f / 31.f) * (float)(n >> 5);
                else if (c == FIN_ + 1) v = -1.f + (2.f / 31.f) * (float)(n & 31);
                tile[ci][tx] = v;
            }
            __syncthreads();
            for (int ni = ty; ni < 32; ni += 8)
                g_t[((size_t)b * NTOK_ + n0 + ni) * CPAD_ + c0 + tx] =
                    __float2bfloat16_rn(tile[tx][ni]);
            __syncthreads();
        }
    } else if (blk < 512 + 1728) {
        const int i = (blk - 512) * 256 + threadIdx.x;
        const int r = i / CPAD_, c = i - r * CPAD_;
        const int sel = r >> 9, o = r & 511;
        const float* w = (sel == 0) ? wq : ((sel == 1) ? wk : wv);
        g_w[i] = __float2bfloat16_rn((c < CIN_) ? w[o * CIN_ + c] : 0.f);
    } else {
        const int i = (blk - 512 - 1728) * 256 + threadIdx.x;
        g_wo[i] = __float2bfloat16_rn(wo[i]);
    }
}

// ---------------------------------------------------------------------------
// GEMM: CTA 128x128, 8 warps (4m x 2n), K-chunks 32 (2 k16 steps),
// 3-stage cp.async pipeline, one __syncthreads per chunk, ldmatrix fragments.
#define TSZB (128 * 80)
__global__ __launch_bounds__(256, 2) void qkv_gemm(
    const float* __restrict__ bq, const float* __restrict__ bk, const float* __restrict__ bv)
{
    extern __shared__ uint32_t sm[];
    const uint32_t sb = smem_u32(sm);

    const int tid = threadIdx.x;
    const int warp = tid >> 5, lane = tid & 31;
    const int g = lane >> 2, t4 = lane & 3;
    const int wm = warp & 3, wn = warp >> 2;
    const int nt = blockIdx.x, mt = blockIdx.y, b = blockIdx.z;
    const int sel = mt >> 2;
    const int o0 = (mt & 3) * 128;
    const int n0 = nt * 128;
    const bf16* wsrc = g_w + (size_t)(sel * COUT_ + o0) * CPAD_;
    const bf16* bsrc = g_t + ((size_t)b * NTOK_ + n0) * CPAD_;
    const float* bias = (sel == 0) ? bq : ((sel == 1) ? bk : bv);

    const uint32_t aoff = (uint32_t)((wm * 32 + (lane & 15)) * 80 + (lane >> 4) * 16);
    const uint32_t boff = (uint32_t)((wn * 64 + (lane >> 4) * 8 + (lane & 7)) * 80
                                     + ((lane >> 3) & 1) * 16);

    auto loadAB = [&](int kc, int st) {
        const uint32_t ab = sb + (uint32_t)(st * 2 * TSZB);
        const uint32_t bb = ab + TSZB;
        #pragma unroll
        for (int it = 0; it < 2; it++) {
            const int i = tid + it * 256;
            const int r = i >> 2, c4 = i & 3;
            cp16(ab + (uint32_t)(r * 80 + c4 * 16), wsrc + (size_t)r * CPAD_ + kc * 32 + c4 * 8);
            cp16(bb + (uint32_t)(r * 80 + c4 * 16), bsrc + (size_t)r * CPAD_ + kc * 32 + c4 * 8);
        }
    };

    float c[2][8][4];
    #pragma unroll
    for (int mi = 0; mi < 2; mi++)
        #pragma unroll
        for (int nf = 0; nf < 8; nf++)
            #pragma unroll
            for (int q = 0; q < 4; q++) c[mi][nf][q] = 0.f;

    loadAB(0, 0); CP_COMMIT();
    loadAB(1, 1); CP_COMMIT();

    const int NK = CPAD_ / 32;  // 9
    for (int kc = 0; kc < NK; kc++) {
        if (kc + 1 < NK) CP_WAIT(1); else CP_WAIT(0);
        __syncthreads();
        if (kc + 2 < NK) { loadAB(kc + 2, (kc + 2) % 3); CP_COMMIT(); }
        const uint32_t Ab = sb + (uint32_t)((kc % 3) * 2 * TSZB);
        const uint32_t Bb = Ab + TSZB;
        #pragma unroll
        for (int s = 0; s < 2; s++) {
            uint32_t a[2][4];
            ldsm4(a[0], Ab + aoff + s * 32);
            ldsm4(a[1], Ab + aoff + 16 * 80 + s * 32);
            #pragma unroll
            for (int nfp = 0; nfp < 4; nfp++) {
                uint32_t bb4[4];
                ldsm4(bb4, Bb + boff + nfp * 16 * 80 + s * 32);
                mma16(c[0][nfp * 2],     a[0], bb4[0], bb4[1]);
                mma16(c[1][nfp * 2],     a[1], bb4[0], bb4[1]);
                mma16(c[0][nfp * 2 + 1], a[0], bb4[2], bb4[3]);
                mma16(c[1][nfp * 2 + 1], a[1], bb4[2], bb4[3]);
            }
        }
    }
    __syncthreads();

    float* Cs = (float*)sm;   // staging reuse: 128*132*4 = 67584
    if (sel < 2) {
        #pragma unroll
        for (int mi = 0; mi < 2; mi++) {
            const int m0 = wm * 32 + mi * 16;
            const float bv0 = bias[o0 + m0 + g];
            const float bv1 = bias[o0 + m0 + g + 8];
            #pragma unroll
            for (int nf = 0; nf < 8; nf++) {
                const int nn = wn * 64 + nf * 8 + t4 * 2;
                Cs[(nn)     * 132 + m0 + g]     = c[mi][nf][0] + bv0;
                Cs[(nn + 1) * 132 + m0 + g]     = c[mi][nf][1] + bv0;
                Cs[(nn)     * 132 + m0 + g + 8] = c[mi][nf][2] + bv1;
                Cs[(nn + 1) * 132 + m0 + g + 8] = c[mi][nf][3] + bv1;
            }
        }
        __syncthreads();
        bf16* dstbase = (sel == 0) ? g_q : g_k;
        #pragma unroll
        for (int it = 0; it < 16; it++) {
            const int i = tid + it * 256;
            const int nl = i >> 5, m4 = i & 31;
            const float4 cv = *(const float4*)&Cs[nl * 132 + m4 * 4];
            const int o = o0 + m4 * 4;
            const int h = o >> 6, d = o & 63;
            uint2 pk = make_uint2(pack2(cv.x, cv.y), pack2(cv.z, cv.w));
            *(uint2*)&dstbase[(((size_t)b * NH_ + h) * NTOK_ + n0 + nl) * FH_ + d] = pk;
        }
    } else {
        #pragma unroll
        for (int mi = 0; mi < 2; mi++) {
            #pragma unroll
            for (int half = 0; half < 2; half++) {
                const int m = wm * 32 + mi * 16 + g + half * 8;
                const int o = o0 + m;
                const int h = o >> 6, d = o & 63;
                const float bval = bias[o];
                bf16* dst = g_v + (((size_t)b * NH_ + h) * FH_ + d) * NTOK_ + n0;
                #pragma unroll
                for (int nf = 0; nf < 8; nf++) {
                    const int nn = wn * 64 + nf * 8 + t4 * 2;
                    *(uint32_t*)&dst[nn] = pack2(c[mi][nf][half * 2] + bval,
                                                 c[mi][nf][half * 2 + 1] + bval);
                }
            }
        }
    }
}

// ---------------------------------------------------------------------------
// Kernel 2: attention. Register-resident P (S-accum == O-A-fragment layout),
// bf16x2 ex2 for exp, 3-buffer K/V, one barrier per chunk. Smem 55296B.
#define KVSTG 9216     // bytes per K or V stage
__global__ __launch_bounds__(256, 2) void attn_kernel() {
    extern __shared__ uint32_t sm[];
    const uint32_t sb = smem_u32(sm);
    const uint32_t KsB = sb, VsB = sb + 3 * KVSTG;

    const int tid = threadIdx.x;
    const int warp = tid >> 5, lane = tid & 31;
    const int g = lane >> 2, t4 = lane & 3;
    const int m0 = warp * 16;
    const int qt = blockIdx.x, h = blockIdx.y, b = blockIdx.z;
    const size_t hb = (size_t)(b * NH_ + h);
    const bf16* qsrc = g_q + hb * NTOK_ * FH_ + (size_t)qt * 128 * FH_;
    const bf16* ksrc = g_k + hb * NTOK_ * FH_;
    const bf16* vsrc = g_v + hb * FH_ * NTOK_;

    const uint32_t kvoff = (uint32_t)(((lane >> 4) * 8 + (lane & 7)) * 144
                                      + ((lane >> 3) & 1) * 16);

    uint32_t qf[4][4];
    {
        const uint32_t* q0 = (const uint32_t*)(qsrc + (size_t)(m0 + g) * FH_);
        const uint32_t* q1 = (const uint32_t*)(qsrc + (size_t)(m0 + g + 8) * FH_);
        #pragma unroll
        for (int s = 0; s < 4; s++) {
            qf[s][0] = q0[s * 8 + t4];
            qf[s][1] = q1[s * 8 + t4];
            qf[s][2] = q0[s * 8 + t4 + 4];
            qf[s][3] = q1[s * 8 + t4 + 4];
        }
    }

    auto loadKV = [&](int ck, int st) {
        const int c0 = ck * 64;
        #pragma unroll
        for (int it = 0; it < 2; it++) {
            const int i = tid + it * 256;
            const int r = i >> 3, c8 = i & 7;
            cp16(KsB + (uint32_t)(st * KVSTG + r * 144 + c8 * 16),
                 ksrc + (size_t)(c0 + r) * FH_ + c8 * 8);
            cp16(VsB + (uint32_t)(st * KVSTG + r * 144 + c8 * 16),
                 vsrc + (size_t)r * NTOK_ + c0 + c8 * 8);
        }
    };

    float oacc[8][4];
    #pragma unroll
    for (int nf = 0; nf < 8; nf++)
        #pragma unroll
        for (int q = 0; q < 4; q++) oacc[nf][q] = 0.f;
    float l0 = 0.f, l1 = 0.f;

    loadKV(0, 0); CP_COMMIT();
    loadKV(1, 1); CP_COMMIT();

    const float SC = 0.125f * 1.4426950408889634f;   // 1/sqrt(64) * log2(e)

    for (int ck = 0; ck < 16; ck++) {
        if (ck + 1 < 16) CP_WAIT(1); else CP_WAIT(0);
        __syncthreads();
        if (ck + 2 < 16) { loadKV(ck + 2, (ck + 2) % 3); CP_COMMIT(); }
        const uint32_t Kb = KsB + (uint32_t)((ck % 3) * KVSTG);
        const uint32_t Vb = VsB + (uint32_t)((ck % 3) * KVSTG);

        // S = Q K^T
        float sc[8][4];
        #pragma unroll
        for (int nf = 0; nf < 8; nf++)
            #pragma unroll
            for (int q = 0; q < 4; q++) sc[nf][q] = 0.f;
        #pragma unroll
        for (int s = 0; s < 4; s++) {
            #pragma unroll
            for (int nfp = 0; nfp < 4; nfp++) {
                uint32_t bb4[4];
                ldsm4(bb4, Kb + kvoff + nfp * 16 * 144 + s * 32);
                mma16(sc[nfp * 2],     qf[s], bb4[0], bb4[1]);
                mma16(sc[nfp * 2 + 1], qf[s], bb4[2], bb4[3]);
            }
        }

        // P = exp2(S*SC) in bf16x2 pairs, kept in registers (A-fragment layout).
        // pb[nf][0] = rows g (cols 2t4,2t4+1); pb[nf][1] = rows g+8.
        uint32_t pb[8][2];
        float s0 = 0.f, s1 = 0.f;
        #pragma unroll
        for (int nf = 0; nf < 8; nf++) {
            pb[nf][0] = ex2_bf16x2(pack2(sc[nf][0] * SC, sc[nf][1] * SC));
            pb[nf][1] = ex2_bf16x2(pack2(sc[nf][2] * SC, sc[nf][3] * SC));
            const float2 f0 = __bfloat1622float2(*(__nv_bfloat162*)&pb[nf][0]);
            const float2 f1 = __bfloat1622float2(*(__nv_bfloat162*)&pb[nf][1]);
            s0 += f0.x + f0.y;
            s1 += f1.x + f1.y;
        }
        s0 += __shfl_xor_sync(0xffffffffu, s0, 1);
        s0 += __shfl_xor_sync(0xffffffffu, s0, 2);
        s1 += __shfl_xor_sync(0xffffffffu, s1, 1);
        s1 += __shfl_xor_sync(0xffffffffu, s1, 2);
        l0 += s0; l1 += s1;

        // O += P V^T : A directly from pb registers, V frags via ldmatrix
        #pragma unroll
        for (int s = 0; s < 4; s++) {
            const uint32_t pa[4] = { pb[2 * s][0], pb[2 * s][1],
                                     pb[2 * s + 1][0], pb[2 * s + 1][1] };
            #pragma unroll
            for (int nfp = 0; nfp < 4; nfp++) {
                uint32_t bb4[4];
                ldsm4(bb4, Vb + kvoff + nfp * 16 * 144 + s * 32);
                mma16(oacc[nfp * 2],     pa, bb4[0], bb4[1]);
                mma16(oacc[nfp * 2 + 1], pa, bb4[2], bb4[3]);
            }
        }
    }

    const float inv0 = 1.f / l0, inv1 = 1.f / l1;
    bf16* d0 = g_o + ((size_t)b * NTOK_ + qt * 128 + m0 + g) * COUT_ + h * FH_;
    bf16* d1 = d0 + 8 * COUT_;
    #pragma unroll
    for (int nf = 0; nf < 8; nf++) {
        const int dd = nf * 8 + t4 * 2;
        *(uint32_t*)&d0[dd] = pack2(oacc[nf][0] * inv0, oacc[nf][1] * inv0);
        *(uint32_t*)&d1[dd] = pack2(oacc[nf][2] * inv1, oacc[nf][3] * inv1);
    }
}

// ---------------------------------------------------------------------------
// Kernel 3: output projection + bias + residual, 3-stage pipeline.
__global__ __launch_bounds__(256, 2) void oproj_gemm(
    const float* __restrict__ x, const float* __restrict__ bo, float* __restrict__ out)
{
    extern __shared__ uint32_t sm[];
    const uint32_t sb = smem_u32(sm);

    const int tid = threadIdx.x;
    const int warp = tid >> 5, lane = tid & 31;
    const int g = lane >> 2, t4 = lane & 3;
    const int wm = warp & 3, wn = warp >> 2;
    const int nt = blockIdx.x, mt = blockIdx.y, b = blockIdx.z;
    const int o0 = mt * 128, n0 = nt * 128;
    const bf16* asrc = g_wo + (size_t)o0 * COUT_;
    const bf16* bsrc = g_o + ((size_t)b * NTOK_ + n0) * COUT_;

    const uint32_t aoff = (uint32_t)((wm * 32 + (lane & 15)) * 80 + (lane >> 4) * 16);
    const uint32_t boff = (uint32_t)((wn * 64 + (lane >> 4) * 8 + (lane & 7)) * 80
                                     + ((lane >> 3) & 1) * 16);

    auto loadAB = [&](int kc, int st) {
        const uint32_t ab = sb + (uint32_t)(st * 2 * TSZB);
        const uint32_t bb = ab + TSZB;
        #pragma unroll
        for (int it = 0; it < 2; it++) {
            const int i = tid + it * 256;
            const int r = i >> 2, c4 = i & 3;
            cp16(ab + (uint32_t)(r * 80 + c4 * 16), asrc + (size_t)r * COUT_ + kc * 32 + c4 * 8);
            cp16(bb + (uint32_t)(r * 80 + c4 * 16), bsrc + (size_t)r * COUT_ + kc * 32 + c4 * 8);
        }
    };

    float c[2][8][4];
    #pragma unroll
    for (int mi = 0; mi < 2; mi++)
        #pragma unroll
        for (int nf = 0; nf < 8; nf++)
            #pragma unroll
            for (int q = 0; q < 4; q++) c[mi][nf][q] = 0.f;

    loadAB(0, 0); CP_COMMIT();
    loadAB(1, 1); CP_COMMIT();

    const int NK = 16;
    for (int kc = 0; kc < NK; kc++) {
        if (kc + 1 < NK) CP_WAIT(1); else CP_WAIT(0);
        __syncthreads();
        if (kc + 2 < NK) { loadAB(kc + 2, (kc + 2) % 3); CP_COMMIT(); }
        const uint32_t Ab = sb + (uint32_t)((kc % 3) * 2 * TSZB);
        const uint32_t Bb = Ab + TSZB;
        #pragma unroll
        for (int s = 0; s < 2; s++) {
            uint32_t a[2][4];
            ldsm4(a[0], Ab + aoff + s * 32);
            ldsm4(a[1], Ab + aoff + 16 * 80 + s * 32);
            #pragma unroll
            for (int nfp = 0; nfp < 4; nfp++) {
                uint32_t bb4[4];
                ldsm4(bb4, Bb + boff + nfp * 16 * 80 + s * 32);
                mma16(c[0][nfp * 2],     a[0], bb4[0], bb4[1]);
                mma16(c[1][nfp * 2],     a[1], bb4[0], bb4[1]);
                mma16(c[0][nfp * 2 + 1], a[0], bb4[2], bb4[3]);
                mma16(c[1][nfp * 2 + 1], a[1], bb4[2], bb4[3]);
            }
        }
    }

    #pragma unroll
    for (int mi = 0; mi < 2; mi++) {
        #pragma unroll
        for (int half = 0; half < 2; half++) {
            const int m = o0 + wm * 32 + mi * 16 + g + half * 8;
            const float bval = bo[m];
            const float* xr = x + ((size_t)b * FIN_ + m) * NTOK_ + n0;
            float* outr = out + ((size_t)b * FIN_ + m) * NTOK_ + n0;
            #pragma unroll
            for (int nf = 0; nf < 8; nf++) {
                const int nn = wn * 64 + nf * 8 + t4 * 2;
                const float2 xv = *(const float2*)&xr[nn];
                *(float2*)&outr[nn] = make_float2(xv.x + bval + c[mi][nf][half * 2],
                                                  xv.y + bval + c[mi][nf][half * 2 + 1]);
            }
        }
    }
}

// ---------------------------------------------------------------------------
extern "C" void kernel_launch(void* const* d_in, const int* in_sizes, int n_in,
                              void* d_out, int out_size)
{
    const float* x  = (const float*)d_in[0];
    const float* wq = (const float*)d_in[1];
    const float* bq = (const float*)d_in[2];
    const float* wk = (const float*)d_in[3];
    const float* bk = (const float*)d_in[4];
    const float* wv = (const float*)d_in[5];
    const float* bv = (const float*)d_in[6];
    const float* wo = (const float*)d_in[7];
    const float* bo = (const float*)d_in[8];
    float* out = (float*)d_out;

    const int qkv_smem   = 128 * 132 * 4;        // 67584 (pipeline 61440, staging 67584)
    const int oproj_smem = 3 * 2 * TSZB;         // 61440
    const int attn_smem  = 6 * KVSTG;            // 55296
    cudaFuncSetAttribute(qkv_gemm,    cudaFuncAttributeMaxDynamicSharedMemorySize, qkv_smem);
    cudaFuncSetAttribute(oproj_gemm,  cudaFuncAttributeMaxDynamicSharedMemorySize, oproj_smem);
    cudaFuncSetAttribute(attn_kernel, cudaFuncAttributeMaxDynamicSharedMemorySize, attn_smem);

    prep_pack<<<512 + 1728 + 512, 256>>>(x, wq, wk, wv, wo);
    qkv_gemm<<<dim3(8, 12, 16), 256, qkv_smem>>>(bq, bk, bv);
    attn_kernel<<<dim3(8, NH_, B_), 256, attn_smem>>>();
    oproj_gemm<<<dim3(8, 2, 16), 256, oproj_smem>>>(x, bo, out);
}